// round 1
// baseline (speedup 1.0000x reference)
#include <cuda_runtime.h>
#include <math.h>

#define BB 2
#define SS 2048
#define DD 1280
#define HH 20
#define HD 64
#define NTOK (BB*SS)   // 4096

// Scratch for projected Q/K/V in [b][h][s][hd] layout (20 MB each)
__device__ float g_Q[BB*HH*SS*HD];
__device__ float g_K[BB*HH*SS*HD];
__device__ float g_V[BB*HH*SS*HD];

// ---------------------------------------------------------------------------
// Kernel 1: fused QKV projection.
//   blockIdx.z selects {Q,K,V}. Tile: 64 rows (tokens) x 64 cols (one head).
//   Epilogue: +bias, (Q: *HD^-0.5), (Q,K: RoPE via shared-memory stage).
// ---------------------------------------------------------------------------
__global__ __launch_bounds__(256) void proj_kernel(
    const float* __restrict__ X,
    const float* __restrict__ Wq, const float* __restrict__ bq,
    const float* __restrict__ Wk, const float* __restrict__ bk,
    const float* __restrict__ Wv, const float* __restrict__ bv)
{
    const int z = blockIdx.z;
    const float* W    = (z == 0) ? Wq : ((z == 1) ? Wk : Wv);
    const float* bias = (z == 0) ? bq : ((z == 1) ? bk : bv);
    float* out        = (z == 0) ? g_Q : ((z == 1) ? g_K : g_V);

    __shared__ float  As[64][17];     // [m][k], padded
    __shared__ float4 Bs4[16*16];     // [k][n/4] as float4
    __shared__ float  stage[64*65];   // rotary staging, padded
    float* Bsf = (float*)Bs4;

    const int t  = threadIdx.x;
    const int tx = t & 15, ty = t >> 4;
    const int m0 = blockIdx.y * 64;
    const int h  = blockIdx.x;
    const int n0 = h * 64;

    float acc[4][4] = {};

    for (int kt = 0; kt < DD/16; ++kt) {
        int k0 = kt * 16;
        __syncthreads();
        #pragma unroll
        for (int e = t; e < 64*16; e += 256) {
            int r = e >> 4, c = e & 15;
            As[r][c] = X[(size_t)(m0 + r)*DD + k0 + c];
        }
        #pragma unroll
        for (int e = t; e < 16*64; e += 256) {
            int kk = e >> 6, c = e & 63;
            Bsf[kk*64 + c] = W[(size_t)(k0 + kk)*DD + n0 + c];
        }
        __syncthreads();
        #pragma unroll
        for (int kk = 0; kk < 16; ++kk) {
            float4 bv4 = Bs4[kk*16 + tx];
            #pragma unroll
            for (int i = 0; i < 4; ++i) {
                float a = As[ty*4 + i][kk];
                acc[i][0] += a * bv4.x;
                acc[i][1] += a * bv4.y;
                acc[i][2] += a * bv4.z;
                acc[i][3] += a * bv4.w;
            }
        }
    }

    const float scale = (z == 0) ? 0.125f : 1.0f;   // HD^-0.5 = 1/8 for Q
    float bb[4];
    #pragma unroll
    for (int j = 0; j < 4; ++j) bb[j] = bias[n0 + tx*4 + j];

    if (z == 2) {
        // V: no rotary, direct store to [b][h][s][hd]
        #pragma unroll
        for (int i = 0; i < 4; ++i) {
            int m = m0 + ty*4 + i;
            int b = m >> 11, s = m & (SS - 1);
            float* dst = out + ((size_t)(b*HH + h)*SS + s)*HD + tx*4;
            #pragma unroll
            for (int j = 0; j < 4; ++j) dst[j] = acc[i][j] + bb[j];
        }
        return;
    }

    // Q/K: stage the 64x64 head tile, then apply rotary (needs hd <-> hd+-32)
    __syncthreads();
    #pragma unroll
    for (int i = 0; i < 4; ++i)
        #pragma unroll
        for (int j = 0; j < 4; ++j)
            stage[(ty*4 + i)*65 + tx*4 + j] = (acc[i][j] + bb[j]) * scale;
    __syncthreads();

    const float L2_10000_OVER_32 = 0.41524101186092029f; // log2(10000)/32
    #pragma unroll
    for (int i = 0; i < 4; ++i) {
        int m = m0 + ty*4 + i;
        int b = m >> 11, s = m & (SS - 1);
        float* dst = out + ((size_t)(b*HH + h)*SS + s)*HD;
        #pragma unroll
        for (int j = 0; j < 4; ++j) {
            int hd = tx*4 + j;
            float v       = stage[(ty*4 + i)*65 + hd];
            float partner = stage[(ty*4 + i)*65 + ((hd + 32) & 63)];
            float rot = (hd < 32) ? -partner : partner;
            int jj = hd & 31;
            float invf = exp2f(-(float)jj * L2_10000_OVER_32); // 10000^(-jj/32)
            float ang = (float)s * invf;
            float sn, cs;
            sincosf(ang, &sn, &cs);
            dst[hd] = v*cs + rot*sn;
        }
    }
}

// ---------------------------------------------------------------------------
// Kernel 2: attention. One block = 64 query rows of one (b,h).
//   Single-pass softmax (scores are provably small, |s| < ~4), K-tiles of 32.
// ---------------------------------------------------------------------------
__global__ __launch_bounds__(256) void attn_kernel(float* __restrict__ out)
{
    __shared__ float  Qs[64*65];
    __shared__ float  Ks[32*65];
    __shared__ float4 Vs4[32*17];
    __shared__ float  Ps[64*32];

    const int t  = threadIdx.x;
    const int tx = t & 15, ty = t >> 4;
    const int q0 = blockIdx.x * 64;
    const int bh = blockIdx.y;
    const int b  = bh / HH, h = bh % HH;
    const size_t base = (size_t)bh * SS * HD;

    // load Q tile (resident for whole kernel)
    #pragma unroll
    for (int e = t; e < 64*64; e += 256) {
        int r = e >> 6, d = e & 63;
        Qs[r*65 + d] = g_Q[base + (size_t)(q0 + r)*HD + d];
    }
    __syncthreads();

    float o[4][4] = {};
    float dsum[4] = {};
    const int r0 = ty * 4;

    for (int kt = 0; kt < SS/32; ++kt) {
        int kk0 = kt * 32;
        // load K (scalar, padded) and V (float4) tiles
        #pragma unroll
        for (int e = t; e < 32*64; e += 256) {
            int kk = e >> 6, d = e & 63;
            Ks[kk*65 + d] = g_K[base + (size_t)(kk0 + kk)*HD + d];
        }
        #pragma unroll
        for (int e = t; e < 32*16; e += 256) {
            int kk = e >> 4, c4 = e & 15;
            Vs4[kk*17 + c4] =
                ((const float4*)(g_V + base + (size_t)(kk0 + kk)*HD))[c4];
        }
        __syncthreads();

        // S = Q @ K^T : 4 rows x 2 keys per thread
        float s[4][2] = {};
        #pragma unroll
        for (int d = 0; d < 64; ++d) {
            float k0v = Ks[(tx*2 + 0)*65 + d];
            float k1v = Ks[(tx*2 + 1)*65 + d];
            #pragma unroll
            for (int i = 0; i < 4; ++i) {
                float q = Qs[(r0 + i)*65 + d];
                s[i][0] += q * k0v;
                s[i][1] += q * k1v;
            }
        }
        #pragma unroll
        for (int i = 0; i < 4; ++i) {
            Ps[(r0 + i)*32 + tx*2 + 0] = __expf(s[i][0]);
            Ps[(r0 + i)*32 + tx*2 + 1] = __expf(s[i][1]);
        }
        __syncthreads();

        // O += P @ V, denom += rowsum(P)  (denom redundantly per-tx, no reduce)
        #pragma unroll
        for (int k = 0; k < 32; ++k) {
            float4 v = Vs4[k*17 + tx];
            #pragma unroll
            for (int i = 0; i < 4; ++i) {
                float p = Ps[(r0 + i)*32 + k];
                o[i][0] += p * v.x;
                o[i][1] += p * v.y;
                o[i][2] += p * v.z;
                o[i][3] += p * v.w;
                dsum[i] += p;
            }
        }
        __syncthreads();
    }

    #pragma unroll
    for (int i = 0; i < 4; ++i) {
        float inv = 1.0f / dsum[i];
        float* dst = out + (size_t)(b*SS + q0 + r0 + i)*DD + h*HD + tx*4;
        dst[0] = o[i][0] * inv;
        dst[1] = o[i][1] * inv;
        dst[2] = o[i][2] * inv;
        dst[3] = o[i][3] * inv;
    }
}

// ---------------------------------------------------------------------------
extern "C" void kernel_launch(void* const* d_in, const int* in_sizes, int n_in,
                              void* d_out, int out_size)
{
    const float* X  = (const float*)d_in[0];
    const float* Wq = (const float*)d_in[1];
    const float* bq = (const float*)d_in[2];
    const float* Wk = (const float*)d_in[3];
    const float* bk = (const float*)d_in[4];
    const float* Wv = (const float*)d_in[5];
    const float* bv = (const float*)d_in[6];
    float* out = (float*)d_out;

    dim3 g1(HH, NTOK/64, 3);       // (20, 64, 3)
    proj_kernel<<<g1, 256>>>(X, Wq, bq, Wk, bk, Wv, bv);

    dim3 g2(SS/64, BB*HH);         // (32, 40)
    attn_kernel<<<g2, 256>>>(out);
}

// round 2
// speedup vs baseline: 2.0983x; 2.0983x over previous
#include <cuda_runtime.h>
#include <math.h>

#define BB 2
#define SS 2048
#define DD 1280
#define HH 20
#define HD 64
#define NTOK (BB*SS)   // 4096

// Scratch: projected Q/K/V in [b][h][s][hd] layout, fp32
__device__ float g_Q[BB*HH*SS*HD];
__device__ float g_K[BB*HH*SS*HD];
__device__ float g_V[BB*HH*SS*HD];

// ---------------------------------------------------------------------------
// helpers
// ---------------------------------------------------------------------------
__device__ __forceinline__ unsigned f2tf(float f) {
    unsigned u;
    asm("cvt.rna.tf32.f32 %0, %1;" : "=r"(u) : "f"(f));
    return u;
}

__device__ __forceinline__ void mma_tf32(float c[4],
                                         unsigned a0, unsigned a1, unsigned a2, unsigned a3,
                                         unsigned b0, unsigned b1) {
    asm volatile(
        "mma.sync.aligned.m16n8k8.row.col.f32.tf32.tf32.f32 "
        "{%0,%1,%2,%3},{%4,%5,%6,%7},{%8,%9},{%0,%1,%2,%3};\n"
        : "+f"(c[0]), "+f"(c[1]), "+f"(c[2]), "+f"(c[3])
        : "r"(a0), "r"(a1), "r"(a2), "r"(a3), "r"(b0), "r"(b1));
}

// ---------------------------------------------------------------------------
// Kernel 1: fused QKV projection via tf32 mma.
//   grid (20 heads, 32 mtiles, 3 {Q,K,V}); block 256 = 8 warps.
//   Block tile: 128 (tokens) x 64 (one head). Warp tile 32x32.
//   Epilogue: +bias, (Q: *1/8), (Q,K: RoPE via smem stage).
// ---------------------------------------------------------------------------
#define APAD 36   // floats per A row  -> frag banks (4r+c) conflict-free
#define WPAD 72   // floats per W row  -> frag banks (8k+n) conflict-free

__global__ __launch_bounds__(256) void proj_kernel(
    const float* __restrict__ X,
    const float* __restrict__ Wq, const float* __restrict__ bq,
    const float* __restrict__ Wk, const float* __restrict__ bk,
    const float* __restrict__ Wv, const float* __restrict__ bv)
{
    const int z = blockIdx.z;
    const float* W    = (z == 0) ? Wq : ((z == 1) ? Wk : Wv);
    const float* bias = (z == 0) ? bq : ((z == 1) ? bk : bv);
    float* out        = (z == 0) ? g_Q : ((z == 1) ? g_K : g_V);

    // union: GEMM stage (As 128x36 + Ws 32x72 = 27.6KB)  vs rotary stage (33.3KB)
    __shared__ __align__(16) char smbuf[128*65*4];
    unsigned* As   = (unsigned*)smbuf;                    // [128][APAD]
    unsigned* Ws   = (unsigned*)(smbuf + 128*APAD*4);     // [32][WPAD]
    float*   stage = (float*)smbuf;                       // [128][65]

    const int t    = threadIdx.x;
    const int lane = t & 31;
    const int wid  = t >> 5;
    const int wm   = wid >> 1;     // 0..3  -> row offset wm*32
    const int wn   = wid & 1;      // 0..1  -> col offset wn*32
    const int m0   = blockIdx.y * 128;
    const int h    = blockIdx.x;
    const int n0   = h * 64;

    const int lr = lane >> 2;      // 0..7
    const int lc = lane & 3;       // 0..3

    float acc[2][4][4];
    #pragma unroll
    for (int i = 0; i < 2; ++i)
        #pragma unroll
        for (int j = 0; j < 4; ++j)
            #pragma unroll
            for (int k = 0; k < 4; ++k) acc[i][j][k] = 0.f;

    for (int kt = 0; kt < DD/32; ++kt) {
        const int k0 = kt * 32;
        __syncthreads();
        // load X tile 128x32 (1024 float4, 4 per thread)
        #pragma unroll
        for (int i = 0; i < 4; ++i) {
            int idx = t + i*256;
            int r = idx >> 3, c4 = idx & 7;
            float4 v = *(const float4*)(X + (size_t)(m0 + r)*DD + k0 + c4*4);
            unsigned* d = As + r*APAD + c4*4;
            d[0] = f2tf(v.x); d[1] = f2tf(v.y); d[2] = f2tf(v.z); d[3] = f2tf(v.w);
        }
        // load W tile 32x64 (512 float4, 2 per thread)
        #pragma unroll
        for (int i = 0; i < 2; ++i) {
            int idx = t + i*256;
            int r = idx >> 4, c4 = idx & 15;
            float4 v = *(const float4*)(W + (size_t)(k0 + r)*DD + n0 + c4*4);
            unsigned* d = Ws + r*WPAD + c4*4;
            d[0] = f2tf(v.x); d[1] = f2tf(v.y); d[2] = f2tf(v.z); d[3] = f2tf(v.w);
        }
        __syncthreads();

        #pragma unroll
        for (int ks = 0; ks < 4; ++ks) {
            const int kk = ks * 8;
            unsigned a[2][4];
            #pragma unroll
            for (int fm = 0; fm < 2; ++fm) {
                int rb = wm*32 + fm*16;
                a[fm][0] = As[(rb + lr    )*APAD + kk + lc    ];
                a[fm][1] = As[(rb + lr + 8)*APAD + kk + lc    ];
                a[fm][2] = As[(rb + lr    )*APAD + kk + lc + 4];
                a[fm][3] = As[(rb + lr + 8)*APAD + kk + lc + 4];
            }
            #pragma unroll
            for (int fn = 0; fn < 4; ++fn) {
                int nb = wn*32 + fn*8 + lr;
                unsigned b0 = Ws[(kk + lc    )*WPAD + nb];
                unsigned b1 = Ws[(kk + lc + 4)*WPAD + nb];
                #pragma unroll
                for (int fm = 0; fm < 2; ++fm)
                    mma_tf32(acc[fm][fn], a[fm][0], a[fm][1], a[fm][2], a[fm][3], b0, b1);
            }
        }
    }

    const float scale = (z == 0) ? 0.125f : 1.0f;

    if (z == 2) {
        // V: bias, direct store
        #pragma unroll
        for (int fm = 0; fm < 2; ++fm)
            #pragma unroll
            for (int fn = 0; fn < 4; ++fn) {
                #pragma unroll
                for (int k = 0; k < 4; ++k) {
                    int row = wm*32 + fm*16 + lr + ((k >= 2) ? 8 : 0);
                    int col = wn*32 + fn*8 + 2*lc + (k & 1);
                    int m = m0 + row;
                    int b = m >> 11, s = m & (SS - 1);
                    out[((size_t)(b*HH + h)*SS + s)*HD + col] = acc[fm][fn][k] + bias[n0 + col];
                }
            }
        return;
    }

    // Q/K: stage with bias+scale, then RoPE
    __syncthreads();   // all frag reads done before overwriting smem
    #pragma unroll
    for (int fm = 0; fm < 2; ++fm)
        #pragma unroll
        for (int fn = 0; fn < 4; ++fn)
            #pragma unroll
            for (int k = 0; k < 4; ++k) {
                int row = wm*32 + fm*16 + lr + ((k >= 2) ? 8 : 0);
                int col = wn*32 + fn*8 + 2*lc + (k & 1);
                stage[row*65 + col] = (acc[fm][fn][k] + bias[n0 + col]) * scale;
            }
    __syncthreads();

    const float L2C = 0.41524101186092029f;  // log2(10000)/32
    #pragma unroll
    for (int e = t; e < 128*64; e += 256) {
        int r = e >> 6, c = e & 63;
        float v       = stage[r*65 + c];
        float partner = stage[r*65 + ((c + 32) & 63)];
        float rot = (c < 32) ? -partner : partner;
        int jj = c & 31;
        float invf = exp2f(-(float)jj * L2C);
        int m = m0 + r;
        int b = m >> 11, s = m & (SS - 1);
        float sn, cs;
        sincosf((float)s * invf, &sn, &cs);
        out[((size_t)(b*HH + h)*SS + s)*HD + c] = v*cs + rot*sn;
    }
}

// ---------------------------------------------------------------------------
// Kernel 2: attention via tf32 mma. One block = 64 q-rows of one (b,h).
//   Single-pass softmax. K-chunks of 64. 8 warps, warp tile 16x32.
//   Dynamic smem: Qs/Ks/VsT/Ps each [64][72] u32 + dsum[64].
// ---------------------------------------------------------------------------
#define SP 72
extern __shared__ unsigned smext[];

__global__ __launch_bounds__(256) void attn_kernel(float* __restrict__ out)
{
    unsigned* Qs  = smext;                 // [64][SP] tf32
    unsigned* Ks  = smext + 64*SP;         // [64][SP] tf32
    unsigned* VsT = smext + 2*64*SP;       // [d][key] tf32 (transposed)
    unsigned* Ps  = smext + 3*64*SP;       // [q][key] tf32
    float*   dss  = (float*)(smext + 4*64*SP);  // [64]

    const int t    = threadIdx.x;
    const int lane = t & 31;
    const int wid  = t >> 5;
    const int wm   = wid >> 1;     // rows wm*16
    const int wn   = wid & 1;      // cols wn*32
    const int lr = lane >> 2, lc = lane & 3;

    const int q0 = blockIdx.x * 64;
    const int bh = blockIdx.y;
    const int b  = bh / HH, h = bh % HH;
    const size_t base = (size_t)bh * SS * HD;

    if (t < 64) dss[t] = 0.f;

    // Q tile: 64x64 = 1024 float4, 4/thread
    #pragma unroll
    for (int i = 0; i < 4; ++i) {
        int idx = t + i*256;
        int r = idx >> 4, c4 = idx & 15;
        float4 v = *(const float4*)(g_Q + base + (size_t)(q0 + r)*HD + c4*4);
        unsigned* d = Qs + r*SP + c4*4;
        d[0] = f2tf(v.x); d[1] = f2tf(v.y); d[2] = f2tf(v.z); d[3] = f2tf(v.w);
    }

    float o[4][4];     // O warp tile 16q x 32d : 4 n-frags
    #pragma unroll
    for (int j = 0; j < 4; ++j)
        #pragma unroll
        for (int k = 0; k < 4; ++k) o[j][k] = 0.f;
    float dsum0 = 0.f, dsum1 = 0.f;   // partial row sums (rows lr, lr+8 of warp tile)

    for (int kt = 0; kt < SS/64; ++kt) {
        const int kk0 = kt * 64;
        __syncthreads();
        // K tile [key][d] and V tile transposed [d][key]
        #pragma unroll
        for (int i = 0; i < 4; ++i) {
            int idx = t + i*256;
            int r = idx >> 4, c4 = idx & 15;
            float4 v = *(const float4*)(g_K + base + (size_t)(kk0 + r)*HD + c4*4);
            unsigned* d = Ks + r*SP + c4*4;
            d[0] = f2tf(v.x); d[1] = f2tf(v.y); d[2] = f2tf(v.z); d[3] = f2tf(v.w);
        }
        #pragma unroll
        for (int i = 0; i < 4; ++i) {
            int idx = t + i*256;
            int r = idx >> 4, c4 = idx & 15;   // r = key, c4*4.. = d
            float4 v = *(const float4*)(g_V + base + (size_t)(kk0 + r)*HD + c4*4);
            VsT[(c4*4 + 0)*SP + r] = f2tf(v.x);
            VsT[(c4*4 + 1)*SP + r] = f2tf(v.y);
            VsT[(c4*4 + 2)*SP + r] = f2tf(v.z);
            VsT[(c4*4 + 3)*SP + r] = f2tf(v.w);
        }
        __syncthreads();

        // S = Q @ K^T : warp tile 16 x 32 (4 n-frags)
        float s[4][4];
        #pragma unroll
        for (int j = 0; j < 4; ++j)
            #pragma unroll
            for (int k = 0; k < 4; ++k) s[j][k] = 0.f;

        #pragma unroll
        for (int ks = 0; ks < 8; ++ks) {
            const int dk = ks * 8;
            int rb = wm*16;
            unsigned a0 = Qs[(rb + lr    )*SP + dk + lc    ];
            unsigned a1 = Qs[(rb + lr + 8)*SP + dk + lc    ];
            unsigned a2 = Qs[(rb + lr    )*SP + dk + lc + 4];
            unsigned a3 = Qs[(rb + lr + 8)*SP + dk + lc + 4];
            #pragma unroll
            for (int fn = 0; fn < 4; ++fn) {
                int nb = wn*32 + fn*8 + lr;    // key index
                unsigned b0 = Ks[nb*SP + dk + lc    ];
                unsigned b1 = Ks[nb*SP + dk + lc + 4];
                mma_tf32(s[fn], a0, a1, a2, a3, b0, b1);
            }
        }

        // P = exp(S); accumulate row sums; stage P to smem (tf32)
        #pragma unroll
        for (int fn = 0; fn < 4; ++fn) {
            float p0 = __expf(s[fn][0]);
            float p1 = __expf(s[fn][1]);
            float p2 = __expf(s[fn][2]);
            float p3 = __expf(s[fn][3]);
            dsum0 += p0 + p1;
            dsum1 += p2 + p3;
            int row = wm*16 + lr;
            int col = wn*32 + fn*8 + 2*lc;
            Ps[(row    )*SP + col    ] = f2tf(p0);
            Ps[(row    )*SP + col + 1] = f2tf(p1);
            Ps[(row + 8)*SP + col    ] = f2tf(p2);
            Ps[(row + 8)*SP + col + 1] = f2tf(p3);
        }
        __syncthreads();   // P complete before cross-warp PV reads

        // O += P @ V : A = Ps[q][key], B = VsT[d][key]
        #pragma unroll
        for (int ks = 0; ks < 8; ++ks) {
            const int kk = ks * 8;
            int rb = wm*16;
            unsigned a0 = Ps[(rb + lr    )*SP + kk + lc    ];
            unsigned a1 = Ps[(rb + lr + 8)*SP + kk + lc    ];
            unsigned a2 = Ps[(rb + lr    )*SP + kk + lc + 4];
            unsigned a3 = Ps[(rb + lr + 8)*SP + kk + lc + 4];
            #pragma unroll
            for (int fn = 0; fn < 4; ++fn) {
                int db = wn*32 + fn*8 + lr;    // d index
                unsigned b0 = VsT[db*SP + kk + lc    ];
                unsigned b1 = VsT[db*SP + kk + lc + 4];
                mma_tf32(o[fn], a0, a1, a2, a3, b0, b1);
            }
        }
    }

    // reduce row sums: within quad (lanes sharing a row), then across wn warps
    dsum0 += __shfl_xor_sync(0xffffffffu, dsum0, 1);
    dsum0 += __shfl_xor_sync(0xffffffffu, dsum0, 2);
    dsum1 += __shfl_xor_sync(0xffffffffu, dsum1, 1);
    dsum1 += __shfl_xor_sync(0xffffffffu, dsum1, 2);
    __syncthreads();
    if (lc == 0) {
        atomicAdd(&dss[wm*16 + lr    ], dsum0);
        atomicAdd(&dss[wm*16 + lr + 8], dsum1);
    }
    __syncthreads();

    // write O / rowsum
    #pragma unroll
    for (int fn = 0; fn < 4; ++fn) {
        int row0 = wm*16 + lr;
        int col  = wn*32 + fn*8 + 2*lc;
        float inv0 = 1.0f / dss[row0];
        float inv1 = 1.0f / dss[row0 + 8];
        float2 v0 = make_float2(o[fn][0]*inv0, o[fn][1]*inv0);
        float2 v1 = make_float2(o[fn][2]*inv1, o[fn][3]*inv1);
        *(float2*)(out + (size_t)(b*SS + q0 + row0    )*DD + h*HD + col) = v0;
        *(float2*)(out + (size_t)(b*SS + q0 + row0 + 8)*DD + h*HD + col) = v1;
    }
}

// ---------------------------------------------------------------------------
extern "C" void kernel_launch(void* const* d_in, const int* in_sizes, int n_in,
                              void* d_out, int out_size)
{
    const float* X  = (const float*)d_in[0];
    const float* Wq = (const float*)d_in[1];
    const float* bq = (const float*)d_in[2];
    const float* Wk = (const float*)d_in[3];
    const float* bk = (const float*)d_in[4];
    const float* Wv = (const float*)d_in[5];
    const float* bv = (const float*)d_in[6];
    float* out = (float*)d_out;

    const int attn_smem = (4*64*SP)*4 + 64*4;   // 73984 + 256 bytes
    cudaFuncSetAttribute(attn_kernel, cudaFuncAttributeMaxDynamicSharedMemorySize, attn_smem);

    dim3 g1(HH, NTOK/128, 3);      // (20, 32, 3)
    proj_kernel<<<g1, 256>>>(X, Wq, bq, Wk, bk, Wv, bv);

    dim3 g2(SS/64, BB*HH);         // (32, 40)
    attn_kernel<<<g2, 256, attn_smem>>>(out);
}

// round 3
// speedup vs baseline: 3.1149x; 1.4845x over previous
#include <cuda_runtime.h>
#include <math.h>

#define BB 2
#define SS 2048
#define DD 1280
#define HH 20
#define HD 64
#define NTOK (BB*SS)   // 4096

// Scratch: projected Q/K/V in [b][h][s][hd] layout, fp32
__device__ float g_Q[BB*HH*SS*HD];
__device__ float g_K[BB*HH*SS*HD];
__device__ float g_V[BB*HH*SS*HD];

// ---------------------------------------------------------------------------
// helpers
// ---------------------------------------------------------------------------
__device__ __forceinline__ unsigned f2tf(float f) {
    unsigned u;
    asm("cvt.rna.tf32.f32 %0, %1;" : "=r"(u) : "f"(f));
    return u;
}
__device__ __forceinline__ uint4 f2tf4(float4 v) {
    return make_uint4(f2tf(v.x), f2tf(v.y), f2tf(v.z), f2tf(v.w));
}

__device__ __forceinline__ void mma_tf32(float c[4],
                                         unsigned a0, unsigned a1, unsigned a2, unsigned a3,
                                         unsigned b0, unsigned b1) {
    asm volatile(
        "mma.sync.aligned.m16n8k8.row.col.f32.tf32.tf32.f32 "
        "{%0,%1,%2,%3},{%4,%5,%6,%7},{%8,%9},{%0,%1,%2,%3};\n"
        : "+f"(c[0]), "+f"(c[1]), "+f"(c[2]), "+f"(c[3])
        : "r"(a0), "r"(a1), "r"(a2), "r"(a3), "r"(b0), "r"(b1));
}

// ---------------------------------------------------------------------------
// Kernel 1: fused QKV projection via tf32 mma.
//   grid (20 heads, 32 mtiles, 3 {Q,K,V}); block 256 = 8 warps.
//   Block tile: 128 (tokens) x 64 (one head). Warp tile 32x32.
// ---------------------------------------------------------------------------
#define APAD 36
#define WPAD 72

__global__ __launch_bounds__(256) void proj_kernel(
    const float* __restrict__ X,
    const float* __restrict__ Wq, const float* __restrict__ bq,
    const float* __restrict__ Wk, const float* __restrict__ bk,
    const float* __restrict__ Wv, const float* __restrict__ bv)
{
    const int z = blockIdx.z;
    const float* W    = (z == 0) ? Wq : ((z == 1) ? Wk : Wv);
    const float* bias = (z == 0) ? bq : ((z == 1) ? bk : bv);
    float* out        = (z == 0) ? g_Q : ((z == 1) ? g_K : g_V);

    __shared__ __align__(16) char smbuf[128*65*4];
    unsigned* As   = (unsigned*)smbuf;                    // [128][APAD]
    unsigned* Ws   = (unsigned*)(smbuf + 128*APAD*4);     // [32][WPAD]
    float*   stage = (float*)smbuf;                       // [128][65]

    const int t    = threadIdx.x;
    const int lane = t & 31;
    const int wid  = t >> 5;
    const int wm   = wid >> 1;
    const int wn   = wid & 1;
    const int m0   = blockIdx.y * 128;
    const int h    = blockIdx.x;
    const int n0   = h * 64;
    const int lr = lane >> 2, lc = lane & 3;

    float acc[2][4][4];
    #pragma unroll
    for (int i = 0; i < 2; ++i)
        #pragma unroll
        for (int j = 0; j < 4; ++j)
            #pragma unroll
            for (int k = 0; k < 4; ++k) acc[i][j][k] = 0.f;

    for (int kt = 0; kt < DD/32; ++kt) {
        const int k0 = kt * 32;
        __syncthreads();
        #pragma unroll
        for (int i = 0; i < 4; ++i) {
            int idx = t + i*256;
            int r = idx >> 3, c4 = idx & 7;
            float4 v = *(const float4*)(X + (size_t)(m0 + r)*DD + k0 + c4*4);
            *(uint4*)(As + r*APAD + c4*4) = f2tf4(v);
        }
        #pragma unroll
        for (int i = 0; i < 2; ++i) {
            int idx = t + i*256;
            int r = idx >> 4, c4 = idx & 15;
            float4 v = *(const float4*)(W + (size_t)(k0 + r)*DD + n0 + c4*4);
            *(uint4*)(Ws + r*WPAD + c4*4) = f2tf4(v);
        }
        __syncthreads();

        #pragma unroll
        for (int ks = 0; ks < 4; ++ks) {
            const int kk = ks * 8;
            unsigned a[2][4];
            #pragma unroll
            for (int fm = 0; fm < 2; ++fm) {
                int rb = wm*32 + fm*16;
                a[fm][0] = As[(rb + lr    )*APAD + kk + lc    ];
                a[fm][1] = As[(rb + lr + 8)*APAD + kk + lc    ];
                a[fm][2] = As[(rb + lr    )*APAD + kk + lc + 4];
                a[fm][3] = As[(rb + lr + 8)*APAD + kk + lc + 4];
            }
            #pragma unroll
            for (int fn = 0; fn < 4; ++fn) {
                int nb = wn*32 + fn*8 + lr;
                unsigned b0 = Ws[(kk + lc    )*WPAD + nb];
                unsigned b1 = Ws[(kk + lc + 4)*WPAD + nb];
                #pragma unroll
                for (int fm = 0; fm < 2; ++fm)
                    mma_tf32(acc[fm][fn], a[fm][0], a[fm][1], a[fm][2], a[fm][3], b0, b1);
            }
        }
    }

    const float scale = (z == 0) ? 0.125f : 1.0f;

    if (z == 2) {
        #pragma unroll
        for (int fm = 0; fm < 2; ++fm)
            #pragma unroll
            for (int fn = 0; fn < 4; ++fn)
                #pragma unroll
                for (int k = 0; k < 4; ++k) {
                    int row = wm*32 + fm*16 + lr + ((k >= 2) ? 8 : 0);
                    int col = wn*32 + fn*8 + 2*lc + (k & 1);
                    int m = m0 + row;
                    int b = m >> 11, s = m & (SS - 1);
                    out[((size_t)(b*HH + h)*SS + s)*HD + col] = acc[fm][fn][k] + bias[n0 + col];
                }
        return;
    }

    __syncthreads();
    #pragma unroll
    for (int fm = 0; fm < 2; ++fm)
        #pragma unroll
        for (int fn = 0; fn < 4; ++fn)
            #pragma unroll
            for (int k = 0; k < 4; ++k) {
                int row = wm*32 + fm*16 + lr + ((k >= 2) ? 8 : 0);
                int col = wn*32 + fn*8 + 2*lc + (k & 1);
                stage[row*65 + col] = (acc[fm][fn][k] + bias[n0 + col]) * scale;
            }
    __syncthreads();

    const float L2C = 0.41524101186092029f;  // log2(10000)/32
    #pragma unroll
    for (int e = t; e < 128*64; e += 256) {
        int r = e >> 6, c = e & 63;
        float v       = stage[r*65 + c];
        float partner = stage[r*65 + ((c + 32) & 63)];
        float rot = (c < 32) ? -partner : partner;
        int jj = c & 31;
        float invf = exp2f(-(float)jj * L2C);
        int m = m0 + r;
        int b = m >> 11, s = m & (SS - 1);
        float sn, cs;
        sincosf((float)s * invf, &sn, &cs);
        out[((size_t)(b*HH + h)*SS + s)*HD + c] = v*cs + rot*sn;
    }
}

// ---------------------------------------------------------------------------
// Kernel 2: attention. 64 q-rows per block, key chunks of 64.
//   Q fragments register-resident; V read directly from [key][d]; P reuses Q smem.
//   SP=76 -> conflict-free B-frag loads both GEMMs.
// ---------------------------------------------------------------------------
#define SP 76
extern __shared__ unsigned smext[];

__global__ __launch_bounds__(256) void attn_kernel(float* __restrict__ out)
{
    unsigned* Qs = smext;                 // [64][SP]; reused as Ps after Q hoist
    unsigned* Ps = smext;
    unsigned* Ks = smext + 64*SP;         // [64][SP]
    unsigned* Vs = smext + 2*64*SP;       // [64][SP], natural [key][d]
    float*   dss = (float*)(smext + 3*64*SP);  // [64]

    const int t    = threadIdx.x;
    const int lane = t & 31;
    const int wid  = t >> 5;
    const int wm   = wid >> 1;     // q-row offset 16*wm
    const int wn   = wid & 1;      // key/d offset 32*wn
    const int lr = lane >> 2, lc = lane & 3;

    const int q0 = blockIdx.x * 64;
    const int bh = blockIdx.y;
    const int b  = bh / HH, h = bh % HH;
    const size_t base = (size_t)bh * SS * HD;

    if (t < 64) dss[t] = 0.f;

    // stage Q, then hoist this warp's fragments into registers
    #pragma unroll
    for (int i = 0; i < 4; ++i) {
        int idx = t + i*256;
        int r = idx >> 4, c4 = idx & 15;
        float4 v = *(const float4*)(g_Q + base + (size_t)(q0 + r)*HD + c4*4);
        *(uint4*)(Qs + r*SP + c4*4) = f2tf4(v);
    }
    __syncthreads();

    unsigned qf[8][4];
    {
        const int rb = wm*16;
        #pragma unroll
        for (int ks = 0; ks < 8; ++ks) {
            const int dk = ks*8;
            qf[ks][0] = Qs[(rb + lr    )*SP + dk + lc    ];
            qf[ks][1] = Qs[(rb + lr + 8)*SP + dk + lc    ];
            qf[ks][2] = Qs[(rb + lr    )*SP + dk + lc + 4];
            qf[ks][3] = Qs[(rb + lr + 8)*SP + dk + lc + 4];
        }
    }
    __syncthreads();   // frag reads done before Ps overwrites Qs

    float o[4][4];
    #pragma unroll
    for (int j = 0; j < 4; ++j)
        #pragma unroll
        for (int k = 0; k < 4; ++k) o[j][k] = 0.f;
    float dsum0 = 0.f, dsum1 = 0.f;

    for (int kt = 0; kt < SS/64; ++kt) {
        const int kk0 = kt * 64;
        __syncthreads();   // prev PV done before K/V overwrite
        #pragma unroll
        for (int i = 0; i < 4; ++i) {
            int idx = t + i*256;
            int r = idx >> 4, c4 = idx & 15;
            float4 kv = *(const float4*)(g_K + base + (size_t)(kk0 + r)*HD + c4*4);
            *(uint4*)(Ks + r*SP + c4*4) = f2tf4(kv);
            float4 vv = *(const float4*)(g_V + base + (size_t)(kk0 + r)*HD + c4*4);
            *(uint4*)(Vs + r*SP + c4*4) = f2tf4(vv);
        }
        __syncthreads();

        // S = Q @ K^T : warp tile 16q x 32key
        float s[4][4];
        #pragma unroll
        for (int j = 0; j < 4; ++j)
            #pragma unroll
            for (int k = 0; k < 4; ++k) s[j][k] = 0.f;

        #pragma unroll
        for (int ks = 0; ks < 8; ++ks) {
            const int dk = ks * 8;
            #pragma unroll
            for (int fn = 0; fn < 4; ++fn) {
                int nb = wn*32 + fn*8 + lr;
                unsigned b0 = Ks[nb*SP + dk + lc    ];
                unsigned b1 = Ks[nb*SP + dk + lc + 4];
                mma_tf32(s[fn], qf[ks][0], qf[ks][1], qf[ks][2], qf[ks][3], b0, b1);
            }
        }

        // P = exp(S), accumulate row sums, stage P
        #pragma unroll
        for (int fn = 0; fn < 4; ++fn) {
            float p0 = __expf(s[fn][0]);
            float p1 = __expf(s[fn][1]);
            float p2 = __expf(s[fn][2]);
            float p3 = __expf(s[fn][3]);
            dsum0 += p0 + p1;
            dsum1 += p2 + p3;
            int row = wm*16 + lr;
            int col = wn*32 + fn*8 + 2*lc;
            *(uint2*)(Ps + (row    )*SP + col) = make_uint2(f2tf(p0), f2tf(p1));
            *(uint2*)(Ps + (row + 8)*SP + col) = make_uint2(f2tf(p2), f2tf(p3));
        }
        __syncthreads();   // P complete before cross-warp PV

        // O += P @ V : A = Ps[q][key], B = V[key][d] read natural
        #pragma unroll
        for (int ks = 0; ks < 8; ++ks) {
            const int kk = ks * 8;
            const int rb = wm*16;
            unsigned a0 = Ps[(rb + lr    )*SP + kk + lc    ];
            unsigned a1 = Ps[(rb + lr + 8)*SP + kk + lc    ];
            unsigned a2 = Ps[(rb + lr    )*SP + kk + lc + 4];
            unsigned a3 = Ps[(rb + lr + 8)*SP + kk + lc + 4];
            #pragma unroll
            for (int fn = 0; fn < 4; ++fn) {
                int db = wn*32 + fn*8 + lr;
                unsigned b0 = Vs[(kk + lc    )*SP + db];
                unsigned b1 = Vs[(kk + lc + 4)*SP + db];
                mma_tf32(o[fn], a0, a1, a2, a3, b0, b1);
            }
        }
    }

    // reduce row sums within quad, then across the two wn warps
    dsum0 += __shfl_xor_sync(0xffffffffu, dsum0, 1);
    dsum0 += __shfl_xor_sync(0xffffffffu, dsum0, 2);
    dsum1 += __shfl_xor_sync(0xffffffffu, dsum1, 1);
    dsum1 += __shfl_xor_sync(0xffffffffu, dsum1, 2);
    __syncthreads();
    if (lc == 0) {
        atomicAdd(&dss[wm*16 + lr    ], dsum0);
        atomicAdd(&dss[wm*16 + lr + 8], dsum1);
    }
    __syncthreads();

    #pragma unroll
    for (int fn = 0; fn < 4; ++fn) {
        int row0 = wm*16 + lr;
        int col  = wn*32 + fn*8 + 2*lc;
        float inv0 = 1.0f / dss[row0];
        float inv1 = 1.0f / dss[row0 + 8];
        float2 v0 = make_float2(o[fn][0]*inv0, o[fn][1]*inv0);
        float2 v1 = make_float2(o[fn][2]*inv1, o[fn][3]*inv1);
        *(float2*)(out + (size_t)(b*SS + q0 + row0    )*DD + h*HD + col) = v0;
        *(float2*)(out + (size_t)(b*SS + q0 + row0 + 8)*DD + h*HD + col) = v1;
    }
}

// ---------------------------------------------------------------------------
extern "C" void kernel_launch(void* const* d_in, const int* in_sizes, int n_in,
                              void* d_out, int out_size)
{
    const float* X  = (const float*)d_in[0];
    const float* Wq = (const float*)d_in[1];
    const float* bq = (const float*)d_in[2];
    const float* Wk = (const float*)d_in[3];
    const float* bk = (const float*)d_in[4];
    const float* Wv = (const float*)d_in[5];
    const float* bv = (const float*)d_in[6];
    float* out = (float*)d_out;

    const int attn_smem = (3*64*SP)*4 + 64*4;
    cudaFuncSetAttribute(attn_kernel, cudaFuncAttributeMaxDynamicSharedMemorySize, attn_smem);

    dim3 g1(HH, NTOK/128, 3);      // (20, 32, 3)
    proj_kernel<<<g1, 256>>>(X, Wq, bq, Wk, bk, Wv, bv);

    dim3 g2(SS/64, BB*HH);         // (32, 40)
    attn_kernel<<<g2, 256, attn_smem>>>(out);
}

// round 4
// speedup vs baseline: 5.6510x; 1.8142x over previous
#include <cuda_runtime.h>
#include <cuda_fp16.h>
#include <math.h>

#define BB 2
#define SS 2048
#define DD 1280
#define HH 20
#define HD 64
#define NTOK (BB*SS)   // 4096

// Scratch: projected Q/K/V in [b][h][s][hd] layout, fp32
__device__ float g_Q[BB*HH*SS*HD];
__device__ float g_K[BB*HH*SS*HD];
__device__ float g_V[BB*HH*SS*HD];

// ---------------------------------------------------------------------------
// helpers
// ---------------------------------------------------------------------------
__device__ __forceinline__ unsigned s2u(const void* p) {
    return (unsigned)__cvta_generic_to_shared(p);
}
__device__ __forceinline__ uint2 f4toh4(float4 v) {
    __half2 a = __floats2half2_rn(v.x, v.y);
    __half2 b = __floats2half2_rn(v.z, v.w);
    uint2 r;
    r.x = *(unsigned*)&a;
    r.y = *(unsigned*)&b;
    return r;
}
__device__ __forceinline__ unsigned packh2(float x, float y) {
    __half2 h = __floats2half2_rn(x, y);
    return *(unsigned*)&h;
}

__device__ __forceinline__ void mma_f16(float c[4],
                                        unsigned a0, unsigned a1, unsigned a2, unsigned a3,
                                        unsigned b0, unsigned b1) {
    asm volatile(
        "mma.sync.aligned.m16n8k16.row.col.f32.f16.f16.f32 "
        "{%0,%1,%2,%3},{%4,%5,%6,%7},{%8,%9},{%0,%1,%2,%3};\n"
        : "+f"(c[0]), "+f"(c[1]), "+f"(c[2]), "+f"(c[3])
        : "r"(a0), "r"(a1), "r"(a2), "r"(a3), "r"(b0), "r"(b1));
}

__device__ __forceinline__ void ldsm4(unsigned& r0, unsigned& r1, unsigned& r2, unsigned& r3,
                                      unsigned addr) {
    asm volatile("ldmatrix.sync.aligned.m8n8.x4.shared.b16 {%0,%1,%2,%3},[%4];"
                 : "=r"(r0), "=r"(r1), "=r"(r2), "=r"(r3) : "r"(addr));
}
__device__ __forceinline__ void ldsm4t(unsigned& r0, unsigned& r1, unsigned& r2, unsigned& r3,
                                       unsigned addr) {
    asm volatile("ldmatrix.sync.aligned.m8n8.x4.trans.shared.b16 {%0,%1,%2,%3},[%4];"
                 : "=r"(r0), "=r"(r1), "=r"(r2), "=r"(r3) : "r"(addr));
}

// ---------------------------------------------------------------------------
// Kernel 1: fused QKV projection, fp16 mma + ldmatrix.
//   Block tile 128(tokens) x 64(one head), k-chunks of 32. Warp tile 32x32.
// ---------------------------------------------------------------------------
#define APADH 40   // halves per A row (80B stride -> distinct banks)
#define WPADH 72   // halves per W row (144B stride -> distinct banks)

__global__ __launch_bounds__(256) void proj_kernel(
    const float* __restrict__ X,
    const float* __restrict__ Wq, const float* __restrict__ bq,
    const float* __restrict__ Wk, const float* __restrict__ bk,
    const float* __restrict__ Wv, const float* __restrict__ bv)
{
    const int z = blockIdx.z;
    const float* W    = (z == 0) ? Wq : ((z == 1) ? Wk : Wv);
    const float* bias = (z == 0) ? bq : ((z == 1) ? bk : bv);
    float* out        = (z == 0) ? g_Q : ((z == 1) ? g_K : g_V);

    __shared__ __align__(16) char smbuf[128*65*4];   // GEMM stage / rotary stage union
    __half* As   = (__half*)smbuf;                    // [128][APADH]
    __half* Ws   = (__half*)(smbuf + 128*APADH*2);    // [32][WPADH]
    float* stage = (float*)smbuf;                     // [128][65]

    const int t    = threadIdx.x;
    const int lane = t & 31;
    const int wid  = t >> 5;
    const int wm   = wid >> 1;
    const int wn   = wid & 1;
    const int m0   = blockIdx.y * 128;
    const int h    = blockIdx.x;
    const int n0   = h * 64;
    const int lr = lane >> 2, lc = lane & 3;

    const unsigned abase = s2u(As);
    const unsigned wbase = s2u(Ws);

    float acc[2][4][4];
    #pragma unroll
    for (int i = 0; i < 2; ++i)
        #pragma unroll
        for (int j = 0; j < 4; ++j)
            #pragma unroll
            for (int k = 0; k < 4; ++k) acc[i][j][k] = 0.f;

    for (int kt = 0; kt < DD/32; ++kt) {
        const int k0 = kt * 32;
        __syncthreads();
        // X tile 128x32 -> fp16
        #pragma unroll
        for (int i = 0; i < 4; ++i) {
            int idx = t + i*256;
            int r = idx >> 3, c4 = idx & 7;
            float4 v = *(const float4*)(X + (size_t)(m0 + r)*DD + k0 + c4*4);
            *(uint2*)(As + r*APADH + c4*4) = f4toh4(v);
        }
        // W tile 32x64 -> fp16 (natural [k][n])
        #pragma unroll
        for (int i = 0; i < 2; ++i) {
            int idx = t + i*256;
            int r = idx >> 4, c4 = idx & 15;
            float4 v = *(const float4*)(W + (size_t)(k0 + r)*DD + n0 + c4*4);
            *(uint2*)(Ws + r*WPADH + c4*4) = f4toh4(v);
        }
        __syncthreads();

        #pragma unroll
        for (int ks = 0; ks < 2; ++ks) {
            const int kk = ks * 16;
            unsigned a[2][4];
            #pragma unroll
            for (int fm = 0; fm < 2; ++fm) {
                int row = wm*32 + fm*16 + (lane & 15);
                int col = kk + ((lane >> 4) << 3);
                ldsm4(a[fm][0], a[fm][1], a[fm][2], a[fm][3],
                      abase + (row*APADH + col)*2);
            }
            #pragma unroll
            for (int fnp = 0; fnp < 2; ++fnp) {
                int nb0 = wn*32 + fnp*16;
                int row = kk + (lane & 7) + (((lane >> 3) & 1) << 3);
                int col = nb0 + ((lane >> 4) << 3);
                unsigned b0, b1, b2, b3;
                ldsm4t(b0, b1, b2, b3, wbase + (row*WPADH + col)*2);
                #pragma unroll
                for (int fm = 0; fm < 2; ++fm) {
                    mma_f16(acc[fm][2*fnp    ], a[fm][0], a[fm][1], a[fm][2], a[fm][3], b0, b1);
                    mma_f16(acc[fm][2*fnp + 1], a[fm][0], a[fm][1], a[fm][2], a[fm][3], b2, b3);
                }
            }
        }
    }

    const float scale = (z == 0) ? 0.125f : 1.0f;

    if (z == 2) {
        #pragma unroll
        for (int fm = 0; fm < 2; ++fm)
            #pragma unroll
            for (int fn = 0; fn < 4; ++fn)
                #pragma unroll
                for (int k = 0; k < 4; ++k) {
                    int row = wm*32 + fm*16 + lr + ((k >= 2) ? 8 : 0);
                    int col = wn*32 + fn*8 + 2*lc + (k & 1);
                    int m = m0 + row;
                    int b = m >> 11, s = m & (SS - 1);
                    out[((size_t)(b*HH + h)*SS + s)*HD + col] = acc[fm][fn][k] + bias[n0 + col];
                }
        return;
    }

    __syncthreads();
    #pragma unroll
    for (int fm = 0; fm < 2; ++fm)
        #pragma unroll
        for (int fn = 0; fn < 4; ++fn)
            #pragma unroll
            for (int k = 0; k < 4; ++k) {
                int row = wm*32 + fm*16 + lr + ((k >= 2) ? 8 : 0);
                int col = wn*32 + fn*8 + 2*lc + (k & 1);
                stage[row*65 + col] = (acc[fm][fn][k] + bias[n0 + col]) * scale;
            }
    __syncthreads();

    const float L2C = 0.41524101186092029f;  // log2(10000)/32
    #pragma unroll
    for (int e = t; e < 128*64; e += 256) {
        int r = e >> 6, c = e & 63;
        float v       = stage[r*65 + c];
        float partner = stage[r*65 + ((c + 32) & 63)];
        float rot = (c < 32) ? -partner : partner;
        int jj = c & 31;
        float invf = exp2f(-(float)jj * L2C);
        int m = m0 + r;
        int b = m >> 11, s = m & (SS - 1);
        float sn, cs;
        sincosf((float)s * invf, &sn, &cs);
        out[((size_t)(b*HH + h)*SS + s)*HD + c] = v*cs + rot*sn;
    }
}

// ---------------------------------------------------------------------------
// Kernel 2: attention, fp16 mma + ldmatrix. 64 q-rows/block, key chunks of 64.
//   Q frags register-hoisted; K natural [key][d] (ldsm); V natural (ldsm.trans);
//   P reuses Q smem.
// ---------------------------------------------------------------------------
#define SPH 72   // halves per row (144B stride)
extern __shared__ __half smh[];

__global__ __launch_bounds__(256) void attn_kernel(float* __restrict__ out)
{
    __half* Qs = smh;                 // [64][SPH]; reused as Ps
    __half* Ps = smh;
    __half* Ks = smh + 64*SPH;        // [64][SPH]
    __half* Vs = smh + 2*64*SPH;      // [64][SPH]
    float* dss = (float*)(smh + 3*64*SPH);  // [64]

    const int t    = threadIdx.x;
    const int lane = t & 31;
    const int wid  = t >> 5;
    const int wm   = wid >> 1;     // q-row offset 16*wm
    const int wn   = wid & 1;      // key/d offset 32*wn
    const int lr = lane >> 2, lc = lane & 3;

    const int q0 = blockIdx.x * 64;
    const int bh = blockIdx.y;
    const int b  = bh / HH, h = bh % HH;
    const size_t base = (size_t)bh * SS * HD;

    const unsigned pbase = s2u(Ps);
    const unsigned kbase = s2u(Ks);
    const unsigned vbase = s2u(Vs);

    if (t < 64) dss[t] = 0.f;

    // stage Q (fp16), hoist this warp's A-fragments
    #pragma unroll
    for (int i = 0; i < 4; ++i) {
        int idx = t + i*256;
        int r = idx >> 4, c4 = idx & 15;
        float4 v = *(const float4*)(g_Q + base + (size_t)(q0 + r)*HD + c4*4);
        *(uint2*)(Qs + r*SPH + c4*4) = f4toh4(v);
    }
    __syncthreads();

    unsigned qf[4][4];
    {
        const int rb = wm*16;
        #pragma unroll
        for (int ks = 0; ks < 4; ++ks) {
            int row = rb + (lane & 15);
            int col = ks*16 + ((lane >> 4) << 3);
            ldsm4(qf[ks][0], qf[ks][1], qf[ks][2], qf[ks][3],
                  pbase + (row*SPH + col)*2);
        }
    }
    __syncthreads();   // frag reads done before Ps overwrites Qs

    float o[4][4];
    #pragma unroll
    for (int j = 0; j < 4; ++j)
        #pragma unroll
        for (int k = 0; k < 4; ++k) o[j][k] = 0.f;
    float dsum0 = 0.f, dsum1 = 0.f;

    for (int kt = 0; kt < SS/64; ++kt) {
        const int kk0 = kt * 64;
        __syncthreads();   // prev PV done before K/V overwrite
        #pragma unroll
        for (int i = 0; i < 4; ++i) {
            int idx = t + i*256;
            int r = idx >> 4, c4 = idx & 15;
            float4 kv = *(const float4*)(g_K + base + (size_t)(kk0 + r)*HD + c4*4);
            *(uint2*)(Ks + r*SPH + c4*4) = f4toh4(kv);
            float4 vv = *(const float4*)(g_V + base + (size_t)(kk0 + r)*HD + c4*4);
            *(uint2*)(Vs + r*SPH + c4*4) = f4toh4(vv);
        }
        __syncthreads();

        // S = Q @ K^T : warp tile 16q x 32key
        float s[4][4];
        #pragma unroll
        for (int j = 0; j < 4; ++j)
            #pragma unroll
            for (int k = 0; k < 4; ++k) s[j][k] = 0.f;

        #pragma unroll
        for (int ks = 0; ks < 4; ++ks) {
            const int dk = ks * 16;
            #pragma unroll
            for (int fnp = 0; fnp < 2; ++fnp) {
                int nb0 = wn*32 + fnp*16;
                int row = nb0 + (lane & 7) + ((lane >> 4) << 3);
                int col = dk + (((lane >> 3) & 1) << 3);
                unsigned b0, b1, b2, b3;
                ldsm4(b0, b1, b2, b3, kbase + (row*SPH + col)*2);
                mma_f16(s[2*fnp    ], qf[ks][0], qf[ks][1], qf[ks][2], qf[ks][3], b0, b1);
                mma_f16(s[2*fnp + 1], qf[ks][0], qf[ks][1], qf[ks][2], qf[ks][3], b2, b3);
            }
        }

        // P = exp(S), accumulate row sums, stage P (fp16)
        #pragma unroll
        for (int fn = 0; fn < 4; ++fn) {
            float p0 = __expf(s[fn][0]);
            float p1 = __expf(s[fn][1]);
            float p2 = __expf(s[fn][2]);
            float p3 = __expf(s[fn][3]);
            dsum0 += p0 + p1;
            dsum1 += p2 + p3;
            int row = wm*16 + lr;
            int col = wn*32 + fn*8 + 2*lc;
            *(unsigned*)(Ps + (row    )*SPH + col) = packh2(p0, p1);
            *(unsigned*)(Ps + (row + 8)*SPH + col) = packh2(p2, p3);
        }
        __syncthreads();   // P complete before cross-warp PV

        // O += P @ V : A from Ps (ldsm), B from natural V (ldsm.trans)
        #pragma unroll
        for (int ks = 0; ks < 4; ++ks) {
            const int kk = ks * 16;
            unsigned a0, a1, a2, a3;
            {
                int row = wm*16 + (lane & 15);
                int col = kk + ((lane >> 4) << 3);
                ldsm4(a0, a1, a2, a3, pbase + (row*SPH + col)*2);
            }
            #pragma unroll
            for (int fnp = 0; fnp < 2; ++fnp) {
                int db0 = wn*32 + fnp*16;
                int row = kk + (lane & 7) + (((lane >> 3) & 1) << 3);
                int col = db0 + ((lane >> 4) << 3);
                unsigned b0, b1, b2, b3;
                ldsm4t(b0, b1, b2, b3, vbase + (row*SPH + col)*2);
                mma_f16(o[2*fnp    ], a0, a1, a2, a3, b0, b1);
                mma_f16(o[2*fnp + 1], a0, a1, a2, a3, b2, b3);
            }
        }
    }

    // reduce row sums within quad, then across the two wn warps
    dsum0 += __shfl_xor_sync(0xffffffffu, dsum0, 1);
    dsum0 += __shfl_xor_sync(0xffffffffu, dsum0, 2);
    dsum1 += __shfl_xor_sync(0xffffffffu, dsum1, 1);
    dsum1 += __shfl_xor_sync(0xffffffffu, dsum1, 2);
    __syncthreads();
    if (lc == 0) {
        atomicAdd(&dss[wm*16 + lr    ], dsum0);
        atomicAdd(&dss[wm*16 + lr + 8], dsum1);
    }
    __syncthreads();

    #pragma unroll
    for (int fn = 0; fn < 4; ++fn) {
        int row0 = wm*16 + lr;
        int col  = wn*32 + fn*8 + 2*lc;
        float inv0 = 1.0f / dss[row0];
        float inv1 = 1.0f / dss[row0 + 8];
        float2 v0 = make_float2(o[fn][0]*inv0, o[fn][1]*inv0);
        float2 v1 = make_float2(o[fn][2]*inv1, o[fn][3]*inv1);
        *(float2*)(out + (size_t)(b*SS + q0 + row0    )*DD + h*HD + col) = v0;
        *(float2*)(out + (size_t)(b*SS + q0 + row0 + 8)*DD + h*HD + col) = v1;
    }
}

// ---------------------------------------------------------------------------
extern "C" void kernel_launch(void* const* d_in, const int* in_sizes, int n_in,
                              void* d_out, int out_size)
{
    const float* X  = (const float*)d_in[0];
    const float* Wq = (const float*)d_in[1];
    const float* bq = (const float*)d_in[2];
    const float* Wk = (const float*)d_in[3];
    const float* bk = (const float*)d_in[4];
    const float* Wv = (const float*)d_in[5];
    const float* bv = (const float*)d_in[6];
    float* out = (float*)d_out;

    const int attn_smem = 3*64*SPH*2 + 64*4;   // 27648 + 256 bytes
    cudaFuncSetAttribute(attn_kernel, cudaFuncAttributeMaxDynamicSharedMemorySize, attn_smem);

    dim3 g1(HH, NTOK/128, 3);      // (20, 32, 3)
    proj_kernel<<<g1, 256>>>(X, Wq, bq, Wk, bk, Wv, bv);

    dim3 g2(SS/64, BB*HH);         // (32, 40)
    attn_kernel<<<g2, 256, attn_smem>>>(out);
}

// round 6
// speedup vs baseline: 6.5709x; 1.1628x over previous
#include <cuda_runtime.h>
#include <cuda_fp16.h>
#include <math.h>

#define BB 2
#define SS 2048
#define DD 1280
#define HH 20
#define HD 64
#define NTOK (BB*SS)   // 4096

// fp16 scratch
__device__ __half g_Xh[NTOK*DD];          // hidden states, fp16
__device__ __half g_Wh[3*DD*DD];          // Wq|Wk|Wv, fp16
__device__ __half g_Qh[BB*HH*SS*HD];      // [b][h][s][hd]
__device__ __half g_Kh[BB*HH*SS*HD];
__device__ __half g_Vh[BB*HH*SS*HD];
__device__ float2 g_rope[SS*32];          // (cos, sin) per (s, jj)

// ---------------------------------------------------------------------------
// helpers
// ---------------------------------------------------------------------------
__device__ __forceinline__ unsigned s2u(const void* p) {
    return (unsigned)__cvta_generic_to_shared(p);
}
__device__ __forceinline__ unsigned packh2(float x, float y) {
    __half2 h = __floats2half2_rn(x, y);
    return *(unsigned*)&h;
}
__device__ __forceinline__ void mma_f16(float c[4],
                                        unsigned a0, unsigned a1, unsigned a2, unsigned a3,
                                        unsigned b0, unsigned b1) {
    asm volatile(
        "mma.sync.aligned.m16n8k16.row.col.f32.f16.f16.f32 "
        "{%0,%1,%2,%3},{%4,%5,%6,%7},{%8,%9},{%0,%1,%2,%3};\n"
        : "+f"(c[0]), "+f"(c[1]), "+f"(c[2]), "+f"(c[3])
        : "r"(a0), "r"(a1), "r"(a2), "r"(a3), "r"(b0), "r"(b1));
}
__device__ __forceinline__ void ldsm4(unsigned& r0, unsigned& r1, unsigned& r2, unsigned& r3,
                                      unsigned addr) {
    asm volatile("ldmatrix.sync.aligned.m8n8.x4.shared.b16 {%0,%1,%2,%3},[%4];"
                 : "=r"(r0), "=r"(r1), "=r"(r2), "=r"(r3) : "r"(addr));
}
__device__ __forceinline__ void ldsm4t(unsigned& r0, unsigned& r1, unsigned& r2, unsigned& r3,
                                       unsigned addr) {
    asm volatile("ldmatrix.sync.aligned.m8n8.x4.trans.shared.b16 {%0,%1,%2,%3},[%4];"
                 : "=r"(r0), "=r"(r1), "=r"(r2), "=r"(r3) : "r"(addr));
}

// ---------------------------------------------------------------------------
// Kernel 0a: fp32 -> fp16 conversion (X, Wq, Wk, Wv)
// ---------------------------------------------------------------------------
__global__ void cvt_kernel(const float4* __restrict__ src, int mode, int n4)
{
    uint2* dst = (mode == 0) ? (uint2*)g_Xh
                             : (uint2*)(g_Wh + (size_t)(mode - 1)*DD*DD);
    int i = blockIdx.x*blockDim.x + threadIdx.x;
    int stride = gridDim.x*blockDim.x;
    for (; i < n4; i += stride) {
        float4 v = src[i];
        uint2 r;
        r.x = packh2(v.x, v.y);
        r.y = packh2(v.z, v.w);
        dst[i] = r;
    }
}

// Kernel 0b: RoPE table
__global__ void rope_kernel()
{
    int idx = blockIdx.x*blockDim.x + threadIdx.x;
    if (idx >= SS*32) return;
    int s = idx >> 5, jj = idx & 31;
    const float L2C = 0.41524101186092029f;  // log2(10000)/32
    float invf = exp2f(-(float)jj * L2C);
    float sn, cs;
    sincosf((float)s * invf, &sn, &cs);
    g_rope[idx] = make_float2(cs, sn);
}

// ---------------------------------------------------------------------------
// Kernel 1: fused QKV projection (all 3 outputs per block, shared X stage).
//   grid (20 heads, 32 mtiles). Block tile 128x64 per z, warp tile 32x32.
//   Register-prefetch pipeline over 40 k-chunks of 32.
// ---------------------------------------------------------------------------
#define APADH 40   // halves per As row (80B stride)
#define WPADH 72   // halves per Ws row (144B stride)

__global__ __launch_bounds__(256, 1) void proj_kernel(
    const float* __restrict__ bq, const float* __restrict__ bk,
    const float* __restrict__ bv)
{
    __shared__ __align__(16) char smbuf[128*65*4];     // GEMM / rotary union
    __half* As  = (__half*)smbuf;                       // [128][APADH]
    __half* Ws  = (__half*)(smbuf + 128*APADH*2);       // [3][32][WPADH]
    float* stage = (float*)smbuf;                       // [128][65]

    const int t    = threadIdx.x;
    const int lane = t & 31;
    const int wid  = t >> 5;
    const int wm   = wid >> 1;     // 0..3
    const int wn   = wid & 1;      // 0..1
    const int m0   = blockIdx.y * 128;
    const int h    = blockIdx.x;
    const int n0   = h * 64;
    const int lr = lane >> 2, lc = lane & 3;

    const unsigned abase = s2u(As);
    const unsigned wbase = s2u(Ws);

    float acc[3][2][4][4];
    #pragma unroll
    for (int z = 0; z < 3; ++z)
        #pragma unroll
        for (int i = 0; i < 2; ++i)
            #pragma unroll
            for (int j = 0; j < 4; ++j)
                #pragma unroll
                for (int k = 0; k < 4; ++k) acc[z][i][j][k] = 0.f;

    const int rx = t >> 2, cx = t & 3;     // X: rows rx, rx+64, 8-half chunk cx
    const int rw = t >> 3, cw = t & 7;     // W: row rw, chunk cw

    uint4 xr0, xr1, wr0, wr1, wr2;
    xr0 = *(const uint4*)(g_Xh + (size_t)(m0 + rx     )*DD + cx*8);
    xr1 = *(const uint4*)(g_Xh + (size_t)(m0 + rx + 64)*DD + cx*8);
    wr0 = *(const uint4*)(g_Wh +                      (size_t)rw*DD + n0 + cw*8);
    wr1 = *(const uint4*)(g_Wh + (size_t)DD*DD     +  (size_t)rw*DD + n0 + cw*8);
    wr2 = *(const uint4*)(g_Wh + (size_t)2*DD*DD   +  (size_t)rw*DD + n0 + cw*8);

    for (int kt = 0; kt < 40; ++kt) {
        __syncthreads();
        *(uint4*)(As + rx*APADH + cx*8)        = xr0;
        *(uint4*)(As + (rx + 64)*APADH + cx*8) = xr1;
        *(uint4*)(Ws + 0*32*WPADH + rw*WPADH + cw*8) = wr0;
        *(uint4*)(Ws + 1*32*WPADH + rw*WPADH + cw*8) = wr1;
        *(uint4*)(Ws + 2*32*WPADH + rw*WPADH + cw*8) = wr2;
        if (kt < 39) {
            const int k0 = (kt + 1)*32;
            xr0 = *(const uint4*)(g_Xh + (size_t)(m0 + rx     )*DD + k0 + cx*8);
            xr1 = *(const uint4*)(g_Xh + (size_t)(m0 + rx + 64)*DD + k0 + cx*8);
            wr0 = *(const uint4*)(g_Wh +                    (size_t)(k0 + rw)*DD + n0 + cw*8);
            wr1 = *(const uint4*)(g_Wh + (size_t)DD*DD   +  (size_t)(k0 + rw)*DD + n0 + cw*8);
            wr2 = *(const uint4*)(g_Wh + (size_t)2*DD*DD +  (size_t)(k0 + rw)*DD + n0 + cw*8);
        }
        __syncthreads();

        #pragma unroll
        for (int ks = 0; ks < 2; ++ks) {
            const int kk = ks * 16;
            unsigned a[2][4];
            #pragma unroll
            for (int fm = 0; fm < 2; ++fm) {
                int row = wm*32 + fm*16 + (lane & 15);
                int col = kk + ((lane >> 4) << 3);
                ldsm4(a[fm][0], a[fm][1], a[fm][2], a[fm][3],
                      abase + (row*APADH + col)*2);
            }
            #pragma unroll
            for (int z = 0; z < 3; ++z) {
                #pragma unroll
                for (int fnp = 0; fnp < 2; ++fnp) {
                    int row = kk + (lane & 7) + (((lane >> 3) & 1) << 3);
                    int col = wn*32 + fnp*16 + ((lane >> 4) << 3);
                    unsigned b0, b1, b2, b3;
                    ldsm4t(b0, b1, b2, b3,
                           wbase + (z*32*WPADH + row*WPADH + col)*2);
                    #pragma unroll
                    for (int fm = 0; fm < 2; ++fm) {
                        mma_f16(acc[z][fm][2*fnp    ], a[fm][0], a[fm][1], a[fm][2], a[fm][3], b0, b1);
                        mma_f16(acc[z][fm][2*fnp + 1], a[fm][0], a[fm][1], a[fm][2], a[fm][3], b2, b3);
                    }
                }
            }
        }
    }

    // --- epilogues ---
    // Q then K: stage fp32, RoPE via table, store fp16
    #pragma unroll
    for (int z = 0; z < 2; ++z) {
        const float* bias = z ? bk : bq;
        __half* dst       = z ? g_Kh : g_Qh;
        const float scale = z ? 1.0f : 0.125f;
        __syncthreads();
        #pragma unroll
        for (int fm = 0; fm < 2; ++fm)
            #pragma unroll
            for (int fn = 0; fn < 4; ++fn)
                #pragma unroll
                for (int k = 0; k < 4; ++k) {
                    int row = wm*32 + fm*16 + lr + ((k >= 2) ? 8 : 0);
                    int col = wn*32 + fn*8 + 2*lc + (k & 1);
                    stage[row*65 + col] = (acc[z][fm][fn][k] + bias[n0 + col]) * scale;
                }
        __syncthreads();
        #pragma unroll
        for (int i = 0; i < 16; ++i) {
            int idx = t + i*256;          // 128 x 32 col-pairs
            int r = idx >> 5, c = (idx & 31) * 2;
            float v0 = stage[r*65 + c];
            float v1 = stage[r*65 + c + 1];
            float p0 = stage[r*65 + ((c + 32) & 63)];
            float p1 = stage[r*65 + ((c + 33) & 63)];
            if (c < 32) { p0 = -p0; p1 = -p1; }
            int m = m0 + r, b = m >> 11, s = m & (SS - 1);
            float2 cs0 = g_rope[s*32 + (c & 31)];
            float2 cs1 = g_rope[s*32 + ((c + 1) & 31)];
            float r0 = v0*cs0.x + p0*cs0.y;
            float r1 = v1*cs1.x + p1*cs1.y;
            *(unsigned*)(dst + ((size_t)(b*HH + h)*SS + s)*HD + c) = packh2(r0, r1);
        }
    }
    // V: direct fp16 store
    #pragma unroll
    for (int fm = 0; fm < 2; ++fm)
        #pragma unroll
        for (int fn = 0; fn < 4; ++fn) {
            int row0 = wm*32 + fm*16 + lr;
            int col  = wn*32 + fn*8 + 2*lc;
            float b0 = bv[n0 + col], b1 = bv[n0 + col + 1];
            int m = m0 + row0;
            int b = m >> 11, s = m & (SS - 1);
            *(unsigned*)(g_Vh + ((size_t)(b*HH + h)*SS + s)*HD + col) =
                packh2(acc[2][fm][fn][0] + b0, acc[2][fm][fn][1] + b1);
            m = m0 + row0 + 8;
            b = m >> 11; s = m & (SS - 1);
            *(unsigned*)(g_Vh + ((size_t)(b*HH + h)*SS + s)*HD + col) =
                packh2(acc[2][fm][fn][2] + b0, acc[2][fm][fn][3] + b1);
        }
}

// ---------------------------------------------------------------------------
// Kernel 2: attention. 128 q-rows/block, key chunks of 64, warp tile 32x32.
//   Q frags register-hoisted; single-pass softmax; P reuses Q smem region.
// ---------------------------------------------------------------------------
#define SPH 72
extern __shared__ __half smh[];

__global__ __launch_bounds__(256, 2) void attn_kernel(float* __restrict__ out)
{
    __half* Qs = smh;                  // [128][SPH]; reused as Ps
    __half* Ps = smh;
    __half* Ks = smh + 128*SPH;        // [64][SPH]
    __half* Vs = smh + 128*SPH + 64*SPH;
    float* dss = (float*)(smh + 128*SPH + 2*64*SPH);   // [128]

    const int t    = threadIdx.x;
    const int lane = t & 31;
    const int wid  = t >> 5;
    const int wm   = wid >> 1;     // q-row offset 32*wm
    const int wn   = wid & 1;      // key/d offset 32*wn
    const int lr = lane >> 2, lc = lane & 3;

    const int q0 = blockIdx.x * 128;
    const int bh = blockIdx.y;
    const int b  = bh / HH, h = bh % HH;
    const size_t base = (size_t)bh * SS * HD;

    const unsigned pbase = s2u(Ps);
    const unsigned kbase = s2u(Ks);
    const unsigned vbase = s2u(Vs);

    if (t < 128) dss[t] = 0.f;

    // stage Q (fp16 direct copy): 128x8 uint4 chunks
    #pragma unroll
    for (int i = 0; i < 4; ++i) {
        int idx = t + i*256;
        int r = idx >> 3, c8 = idx & 7;
        *(uint4*)(Qs + r*SPH + c8*8) =
            *(const uint4*)(g_Qh + base + (size_t)(q0 + r)*HD + c8*8);
    }
    __syncthreads();

    unsigned qf[2][4][4];
    #pragma unroll
    for (int fm = 0; fm < 2; ++fm)
        #pragma unroll
        for (int ks = 0; ks < 4; ++ks) {
            int row = wm*32 + fm*16 + (lane & 15);
            int col = ks*16 + ((lane >> 4) << 3);
            ldsm4(qf[fm][ks][0], qf[fm][ks][1], qf[fm][ks][2], qf[fm][ks][3],
                  pbase + (row*SPH + col)*2);
        }
    __syncthreads();   // frag reads done before Ps overwrites Qs

    float o[2][4][4];
    #pragma unroll
    for (int i = 0; i < 2; ++i)
        #pragma unroll
        for (int j = 0; j < 4; ++j)
            #pragma unroll
            for (int k = 0; k < 4; ++k) o[i][j][k] = 0.f;
    float dsum[2][2] = {};

    for (int kt = 0; kt < SS/64; ++kt) {
        const int kk0 = kt * 64;
        __syncthreads();   // prev PV done before K/V overwrite
        #pragma unroll
        for (int i = 0; i < 2; ++i) {
            int idx = t + i*256;
            int r = idx >> 3, c8 = idx & 7;
            *(uint4*)(Ks + r*SPH + c8*8) =
                *(const uint4*)(g_Kh + base + (size_t)(kk0 + r)*HD + c8*8);
            *(uint4*)(Vs + r*SPH + c8*8) =
                *(const uint4*)(g_Vh + base + (size_t)(kk0 + r)*HD + c8*8);
        }
        __syncthreads();

        // S = Q @ K^T : warp tile 32q x 32key
        float s[2][4][4];
        #pragma unroll
        for (int i = 0; i < 2; ++i)
            #pragma unroll
            for (int j = 0; j < 4; ++j)
                #pragma unroll
                for (int k = 0; k < 4; ++k) s[i][j][k] = 0.f;

        #pragma unroll
        for (int ks = 0; ks < 4; ++ks) {
            const int dk = ks * 16;
            #pragma unroll
            for (int fnp = 0; fnp < 2; ++fnp) {
                // B-fragment lane mapping (round-4 verified): lane bit4 -> +8 key rows,
                // lane bit3 -> +8 in k (d) dimension.
                int row = wn*32 + fnp*16 + (lane & 7) + ((lane >> 4) << 3);
                int col = dk + (((lane >> 3) & 1) << 3);
                unsigned b0, b1, b2, b3;
                ldsm4(b0, b1, b2, b3, kbase + (row*SPH + col)*2);
                #pragma unroll
                for (int fm = 0; fm < 2; ++fm) {
                    mma_f16(s[fm][2*fnp    ], qf[fm][ks][0], qf[fm][ks][1], qf[fm][ks][2], qf[fm][ks][3], b0, b1);
                    mma_f16(s[fm][2*fnp + 1], qf[fm][ks][0], qf[fm][ks][1], qf[fm][ks][2], qf[fm][ks][3], b2, b3);
                }
            }
        }

        // P = exp(S), accumulate row sums, stage P (fp16)
        #pragma unroll
        for (int fm = 0; fm < 2; ++fm)
            #pragma unroll
            for (int fn = 0; fn < 4; ++fn) {
                float p0 = __expf(s[fm][fn][0]);
                float p1 = __expf(s[fm][fn][1]);
                float p2 = __expf(s[fm][fn][2]);
                float p3 = __expf(s[fm][fn][3]);
                dsum[fm][0] += p0 + p1;
                dsum[fm][1] += p2 + p3;
                int row = wm*32 + fm*16 + lr;
                int col = wn*32 + fn*8 + 2*lc;
                *(unsigned*)(Ps + (row    )*SPH + col) = packh2(p0, p1);
                *(unsigned*)(Ps + (row + 8)*SPH + col) = packh2(p2, p3);
            }
        __syncthreads();   // P complete before cross-warp PV

        // O += P @ V
        #pragma unroll
        for (int ks = 0; ks < 4; ++ks) {
            const int kk = ks * 16;
            unsigned a[2][4];
            #pragma unroll
            for (int fm = 0; fm < 2; ++fm) {
                int row = wm*32 + fm*16 + (lane & 15);
                int col = kk + ((lane >> 4) << 3);
                ldsm4(a[fm][0], a[fm][1], a[fm][2], a[fm][3],
                      pbase + (row*SPH + col)*2);
            }
            #pragma unroll
            for (int fnp = 0; fnp < 2; ++fnp) {
                int row = kk + (lane & 7) + (((lane >> 3) & 1) << 3);
                int col = wn*32 + fnp*16 + ((lane >> 4) << 3);
                unsigned b0, b1, b2, b3;
                ldsm4t(b0, b1, b2, b3, vbase + (row*SPH + col)*2);
                #pragma unroll
                for (int fm = 0; fm < 2; ++fm) {
                    mma_f16(o[fm][2*fnp    ], a[fm][0], a[fm][1], a[fm][2], a[fm][3], b0, b1);
                    mma_f16(o[fm][2*fnp + 1], a[fm][0], a[fm][1], a[fm][2], a[fm][3], b2, b3);
                }
            }
        }
    }

    // reduce row sums: quad shuffle then cross-warp atomics
    #pragma unroll
    for (int fm = 0; fm < 2; ++fm)
        #pragma unroll
        for (int half = 0; half < 2; ++half) {
            dsum[fm][half] += __shfl_xor_sync(0xffffffffu, dsum[fm][half], 1);
            dsum[fm][half] += __shfl_xor_sync(0xffffffffu, dsum[fm][half], 2);
        }
    __syncthreads();
    if (lc == 0) {
        #pragma unroll
        for (int fm = 0; fm < 2; ++fm) {
            atomicAdd(&dss[wm*32 + fm*16 + lr    ], dsum[fm][0]);
            atomicAdd(&dss[wm*32 + fm*16 + lr + 8], dsum[fm][1]);
        }
    }
    __syncthreads();

    #pragma unroll
    for (int fm = 0; fm < 2; ++fm)
        #pragma unroll
        for (int fn = 0; fn < 4; ++fn) {
            int row0 = wm*32 + fm*16 + lr;
            int col  = wn*32 + fn*8 + 2*lc;
            float inv0 = 1.0f / dss[row0];
            float inv1 = 1.0f / dss[row0 + 8];
            float2 v0 = make_float2(o[fm][fn][0]*inv0, o[fm][fn][1]*inv0);
            float2 v1 = make_float2(o[fm][fn][2]*inv1, o[fm][fn][3]*inv1);
            *(float2*)(out + (size_t)(b*SS + q0 + row0    )*DD + h*HD + col) = v0;
            *(float2*)(out + (size_t)(b*SS + q0 + row0 + 8)*DD + h*HD + col) = v1;
        }
}

// ---------------------------------------------------------------------------
extern "C" void kernel_launch(void* const* d_in, const int* in_sizes, int n_in,
                              void* d_out, int out_size)
{
    const float* X  = (const float*)d_in[0];
    const float* Wq = (const float*)d_in[1];
    const float* bq = (const float*)d_in[2];
    const float* Wk = (const float*)d_in[3];
    const float* bk = (const float*)d_in[4];
    const float* Wv = (const float*)d_in[5];
    const float* bv = (const float*)d_in[6];
    float* out = (float*)d_out;

    cvt_kernel<<<1024, 256>>>((const float4*)X,  0, NTOK*DD/4);
    cvt_kernel<<<1024, 256>>>((const float4*)Wq, 1, DD*DD/4);
    cvt_kernel<<<1024, 256>>>((const float4*)Wk, 2, DD*DD/4);
    cvt_kernel<<<1024, 256>>>((const float4*)Wv, 3, DD*DD/4);
    rope_kernel<<<SS*32/256, 256>>>();

    dim3 g1(HH, NTOK/128);         // (20, 32)
    proj_kernel<<<g1, 256>>>(bq, bk, bv);

    const int attn_smem = (128*SPH + 2*64*SPH)*2 + 128*4;   // 37376 B
    cudaFuncSetAttribute(attn_kernel, cudaFuncAttributeMaxDynamicSharedMemorySize, attn_smem);
    dim3 g2(SS/128, BB*HH);        // (16, 40)
    attn_kernel<<<g2, 256, attn_smem>>>(out);
}

// round 8
// speedup vs baseline: 7.0887x; 1.0788x over previous
#include <cuda_runtime.h>
#include <cuda_fp16.h>
#include <math.h>

#define BB 2
#define SS 2048
#define DD 1280
#define HH 20
#define HD 64
#define NTOK (BB*SS)   // 4096

// fp16 scratch
__device__ __half g_Xh[NTOK*DD];          // hidden states, fp16
__device__ __half g_Wh[3*DD*DD];          // Wq|Wk|Wv, fp16
__device__ __half g_Qh[BB*HH*SS*HD];      // [b][h][s][hd]  (Q pre-scaled by log2e/8)
__device__ __half g_Kh[BB*HH*SS*HD];
__device__ __half g_Vh[BB*HH*SS*HD];
__device__ float2 g_rope[SS*32];          // (cos, sin) per (s, jj)

// ---------------------------------------------------------------------------
// helpers
// ---------------------------------------------------------------------------
__device__ __forceinline__ unsigned s2u(const void* p) {
    return (unsigned)__cvta_generic_to_shared(p);
}
__device__ __forceinline__ unsigned packh2(float x, float y) {
    __half2 h = __floats2half2_rn(x, y);
    return *(unsigned*)&h;
}
__device__ __forceinline__ unsigned ex2h2(unsigned a) {
    unsigned d;
    asm volatile("ex2.approx.f16x2 %0, %1;" : "=r"(d) : "r"(a));
    return d;
}
__device__ __forceinline__ void mma_f16(float c[4],
                                        unsigned a0, unsigned a1, unsigned a2, unsigned a3,
                                        unsigned b0, unsigned b1) {
    asm volatile(
        "mma.sync.aligned.m16n8k16.row.col.f32.f16.f16.f32 "
        "{%0,%1,%2,%3},{%4,%5,%6,%7},{%8,%9},{%0,%1,%2,%3};\n"
        : "+f"(c[0]), "+f"(c[1]), "+f"(c[2]), "+f"(c[3])
        : "r"(a0), "r"(a1), "r"(a2), "r"(a3), "r"(b0), "r"(b1));
}
__device__ __forceinline__ void ldsm4(unsigned& r0, unsigned& r1, unsigned& r2, unsigned& r3,
                                      unsigned addr) {
    asm volatile("ldmatrix.sync.aligned.m8n8.x4.shared.b16 {%0,%1,%2,%3},[%4];"
                 : "=r"(r0), "=r"(r1), "=r"(r2), "=r"(r3) : "r"(addr));
}
__device__ __forceinline__ void ldsm4t(unsigned& r0, unsigned& r1, unsigned& r2, unsigned& r3,
                                       unsigned addr) {
    asm volatile("ldmatrix.sync.aligned.m8n8.x4.trans.shared.b16 {%0,%1,%2,%3},[%4];"
                 : "=r"(r0), "=r"(r1), "=r"(r2), "=r"(r3) : "r"(addr));
}
#define CP_ASYNC16(sm, gp) \
    asm volatile("cp.async.cg.shared.global [%0],[%1],16;\n" :: "r"(sm), "l"(gp))
#define CP_COMMIT  asm volatile("cp.async.commit_group;\n" ::: "memory")
#define CP_WAIT1   asm volatile("cp.async.wait_group 1;\n" ::: "memory")

// ---------------------------------------------------------------------------
// Kernel 0a: fp32 -> fp16 conversion of X, Wq, Wk, Wv (single launch)
// ---------------------------------------------------------------------------
#define N4X (NTOK*DD/4)
#define N4W (DD*DD/4)
__global__ void cvt_all_kernel(const float4* __restrict__ X,
                               const float4* __restrict__ Wq,
                               const float4* __restrict__ Wk,
                               const float4* __restrict__ Wv)
{
    int i = blockIdx.x*blockDim.x + threadIdx.x;
    int stride = gridDim.x*blockDim.x;
    const int tot = N4X + 3*N4W;
    for (; i < tot; i += stride) {
        const float4* src;
        uint2* dst;
        int j;
        if (i < N4X)            { src = X;  dst = (uint2*)g_Xh; j = i; }
        else if (i < N4X+N4W)   { src = Wq; dst = (uint2*)g_Wh; j = i - N4X; }
        else if (i < N4X+2*N4W) { src = Wk; dst = (uint2*)(g_Wh + (size_t)DD*DD);   j = i - N4X - N4W; }
        else                    { src = Wv; dst = (uint2*)(g_Wh + (size_t)2*DD*DD); j = i - N4X - 2*N4W; }
        float4 v = src[j];
        uint2 r;
        r.x = packh2(v.x, v.y);
        r.y = packh2(v.z, v.w);
        dst[j] = r;
    }
}

// Kernel 0b: RoPE table
__global__ void rope_kernel()
{
    int idx = blockIdx.x*blockDim.x + threadIdx.x;
    if (idx >= SS*32) return;
    int s = idx >> 5, jj = idx & 31;
    const float L2C = 0.41524101186092029f;  // log2(10000)/32
    float invf = exp2f(-(float)jj * L2C);
    float sn, cs;
    sincosf((float)s * invf, &sn, &cs);
    g_rope[idx] = make_float2(cs, sn);
}

// ---------------------------------------------------------------------------
// Kernel 1: fused QKV projection (Q,K,V per block, shared X stage).
//   grid (20 heads, 32 mtiles). Block tile 128x64 per z, warp tile 32x32.
//   Q output pre-scaled by (1/8)*log2(e) so attention scores are log2-domain.
// ---------------------------------------------------------------------------
#define APADH 40   // halves per As row (80B stride)
#define WPADH 72   // halves per Ws row (144B stride)

__global__ __launch_bounds__(256, 1) void proj_kernel(
    const float* __restrict__ bq, const float* __restrict__ bk,
    const float* __restrict__ bv)
{
    __shared__ __align__(16) char smbuf[128*65*4];     // GEMM / rotary union
    __half* As  = (__half*)smbuf;                       // [128][APADH]
    __half* Ws  = (__half*)(smbuf + 128*APADH*2);       // [3][32][WPADH]
    float* stage = (float*)smbuf;                       // [128][65]

    const int t    = threadIdx.x;
    const int lane = t & 31;
    const int wid  = t >> 5;
    const int wm   = wid >> 1;     // 0..3
    const int wn   = wid & 1;      // 0..1
    const int m0   = blockIdx.y * 128;
    const int h    = blockIdx.x;
    const int n0   = h * 64;
    const int lr = lane >> 2, lc = lane & 3;

    const unsigned abase = s2u(As);
    const unsigned wbase = s2u(Ws);

    float acc[3][2][4][4];
    #pragma unroll
    for (int z = 0; z < 3; ++z)
        #pragma unroll
        for (int i = 0; i < 2; ++i)
            #pragma unroll
            for (int j = 0; j < 4; ++j)
                #pragma unroll
                for (int k = 0; k < 4; ++k) acc[z][i][j][k] = 0.f;

    const int rx = t >> 2, cx = t & 3;     // X: rows rx, rx+64, 8-half chunk cx
    const int rw = t >> 3, cw = t & 7;     // W: row rw, chunk cw

    uint4 xr0, xr1, wr0, wr1, wr2;
    xr0 = *(const uint4*)(g_Xh + (size_t)(m0 + rx     )*DD + cx*8);
    xr1 = *(const uint4*)(g_Xh + (size_t)(m0 + rx + 64)*DD + cx*8);
    wr0 = *(const uint4*)(g_Wh +                      (size_t)rw*DD + n0 + cw*8);
    wr1 = *(const uint4*)(g_Wh + (size_t)DD*DD     +  (size_t)rw*DD + n0 + cw*8);
    wr2 = *(const uint4*)(g_Wh + (size_t)2*DD*DD   +  (size_t)rw*DD + n0 + cw*8);

    for (int kt = 0; kt < 40; ++kt) {
        __syncthreads();
        *(uint4*)(As + rx*APADH + cx*8)        = xr0;
        *(uint4*)(As + (rx + 64)*APADH + cx*8) = xr1;
        *(uint4*)(Ws + 0*32*WPADH + rw*WPADH + cw*8) = wr0;
        *(uint4*)(Ws + 1*32*WPADH + rw*WPADH + cw*8) = wr1;
        *(uint4*)(Ws + 2*32*WPADH + rw*WPADH + cw*8) = wr2;
        if (kt < 39) {
            const int k0 = (kt + 1)*32;
            xr0 = *(const uint4*)(g_Xh + (size_t)(m0 + rx     )*DD + k0 + cx*8);
            xr1 = *(const uint4*)(g_Xh + (size_t)(m0 + rx + 64)*DD + k0 + cx*8);
            wr0 = *(const uint4*)(g_Wh +                    (size_t)(k0 + rw)*DD + n0 + cw*8);
            wr1 = *(const uint4*)(g_Wh + (size_t)DD*DD   +  (size_t)(k0 + rw)*DD + n0 + cw*8);
            wr2 = *(const uint4*)(g_Wh + (size_t)2*DD*DD +  (size_t)(k0 + rw)*DD + n0 + cw*8);
        }
        __syncthreads();

        #pragma unroll
        for (int ks = 0; ks < 2; ++ks) {
            const int kk = ks * 16;
            unsigned a[2][4];
            #pragma unroll
            for (int fm = 0; fm < 2; ++fm) {
                int row = wm*32 + fm*16 + (lane & 15);
                int col = kk + ((lane >> 4) << 3);
                ldsm4(a[fm][0], a[fm][1], a[fm][2], a[fm][3],
                      abase + (row*APADH + col)*2);
            }
            #pragma unroll
            for (int z = 0; z < 3; ++z) {
                #pragma unroll
                for (int fnp = 0; fnp < 2; ++fnp) {
                    int row = kk + (lane & 7) + (((lane >> 3) & 1) << 3);
                    int col = wn*32 + fnp*16 + ((lane >> 4) << 3);
                    unsigned b0, b1, b2, b3;
                    ldsm4t(b0, b1, b2, b3,
                           wbase + (z*32*WPADH + row*WPADH + col)*2);
                    #pragma unroll
                    for (int fm = 0; fm < 2; ++fm) {
                        mma_f16(acc[z][fm][2*fnp    ], a[fm][0], a[fm][1], a[fm][2], a[fm][3], b0, b1);
                        mma_f16(acc[z][fm][2*fnp + 1], a[fm][0], a[fm][1], a[fm][2], a[fm][3], b2, b3);
                    }
                }
            }
        }
    }

    // --- epilogues ---
    // Q then K: stage fp32, RoPE via table, store fp16.
    // Q scale folds in log2(e) so downstream softmax can use ex2.
    #pragma unroll
    for (int z = 0; z < 2; ++z) {
        const float* bias = z ? bk : bq;
        __half* dst       = z ? g_Kh : g_Qh;
        const float scale = z ? 1.0f : 0.125f * 1.4426950408889634f;
        __syncthreads();
        #pragma unroll
        for (int fm = 0; fm < 2; ++fm)
            #pragma unroll
            for (int fn = 0; fn < 4; ++fn)
                #pragma unroll
                for (int k = 0; k < 4; ++k) {
                    int row = wm*32 + fm*16 + lr + ((k >= 2) ? 8 : 0);
                    int col = wn*32 + fn*8 + 2*lc + (k & 1);
                    stage[row*65 + col] = (acc[z][fm][fn][k] + bias[n0 + col]) * scale;
                }
        __syncthreads();
        #pragma unroll
        for (int i = 0; i < 16; ++i) {
            int idx = t + i*256;          // 128 x 32 col-pairs
            int r = idx >> 5, c = (idx & 31) * 2;
            float v0 = stage[r*65 + c];
            float v1 = stage[r*65 + c + 1];
            float p0 = stage[r*65 + ((c + 32) & 63)];
            float p1 = stage[r*65 + ((c + 33) & 63)];
            if (c < 32) { p0 = -p0; p1 = -p1; }
            int m = m0 + r, b = m >> 11, s = m & (SS - 1);
            float2 cs0 = g_rope[s*32 + (c & 31)];
            float2 cs1 = g_rope[s*32 + ((c + 1) & 31)];
            float r0 = v0*cs0.x + p0*cs0.y;
            float r1 = v1*cs1.x + p1*cs1.y;
            *(unsigned*)(dst + ((size_t)(b*HH + h)*SS + s)*HD + c) = packh2(r0, r1);
        }
    }
    // V: direct fp16 store
    #pragma unroll
    for (int fm = 0; fm < 2; ++fm)
        #pragma unroll
        for (int fn = 0; fn < 4; ++fn) {
            int row0 = wm*32 + fm*16 + lr;
            int col  = wn*32 + fn*8 + 2*lc;
            float b0 = bv[n0 + col], b1 = bv[n0 + col + 1];
            int m = m0 + row0;
            int b = m >> 11, s = m & (SS - 1);
            *(unsigned*)(g_Vh + ((size_t)(b*HH + h)*SS + s)*HD + col) =
                packh2(acc[2][fm][fn][0] + b0, acc[2][fm][fn][1] + b1);
            m = m0 + row0 + 8;
            b = m >> 11; s = m & (SS - 1);
            *(unsigned*)(g_Vh + ((size_t)(b*HH + h)*SS + s)*HD + col) =
                packh2(acc[2][fm][fn][2] + b0, acc[2][fm][fn][3] + b1);
        }
}

// ---------------------------------------------------------------------------
// Kernel 2: attention. 128 q-rows/block, key chunks of 64, warp tile 32x32.
//   cp.async double-buffered K/V; ex2.f16x2 softmax; denom via ones-column mma.
// ---------------------------------------------------------------------------
#define SPH 72
#define ONESH2 0x3C003C00u
extern __shared__ __half smh[];

__global__ __launch_bounds__(256, 2) void attn_kernel(float* __restrict__ out)
{
    __half* Qs   = smh;                       // [128][SPH]; reused as Ps
    __half* Ps   = smh;
    __half* Kbuf = smh + 128*SPH;             // [2][64][SPH]
    __half* Vbuf = smh + 128*SPH + 2*64*SPH;  // [2][64][SPH]
    float*  dss  = (float*)(smh + 128*SPH + 4*64*SPH);   // [128]

    const int t    = threadIdx.x;
    const int lane = t & 31;
    const int wid  = t >> 5;
    const int wm   = wid >> 1;     // q-row offset 32*wm
    const int wn   = wid & 1;      // key/d offset 32*wn
    const int lr = lane >> 2, lc = lane & 3;

    const int q0 = blockIdx.x * 128;
    const int bh = blockIdx.y;
    const int b  = bh / HH, h = bh % HH;
    const size_t base = (size_t)bh * SS * HD;

    const unsigned pbase = s2u(Ps);
    const unsigned kbase = s2u(Kbuf);
    const unsigned vbase = s2u(Vbuf);

    const int rt = t >> 3, ct = (t & 7) * 8;   // cp.async tile mapping (64 rows x 8 chunks)

    // stage Q (fp16 direct copy)
    #pragma unroll
    for (int i = 0; i < 4; ++i) {
        int idx = t + i*256;
        int r = idx >> 3, c8 = idx & 7;
        *(uint4*)(Qs + r*SPH + c8*8) =
            *(const uint4*)(g_Qh + base + (size_t)(q0 + r)*HD + c8*8);
    }
    __syncthreads();

    unsigned qf[2][4][4];
    #pragma unroll
    for (int fm = 0; fm < 2; ++fm)
        #pragma unroll
        for (int ks = 0; ks < 4; ++ks) {
            int row = wm*32 + fm*16 + (lane & 15);
            int col = ks*16 + ((lane >> 4) << 3);
            ldsm4(qf[fm][ks][0], qf[fm][ks][1], qf[fm][ks][2], qf[fm][ks][3],
                  pbase + (row*SPH + col)*2);
        }
    __syncthreads();   // frag reads done before Ps overwrites Qs

    // preload tile 0 into buffer 0
    {
        const __half* kg = g_Kh + base;
        const __half* vg = g_Vh + base;
        #pragma unroll
        for (int i = 0; i < 2; ++i) {
            int r = rt + i*32;
            CP_ASYNC16(kbase + (r*SPH + ct)*2, kg + (size_t)r*HD + ct);
            CP_ASYNC16(vbase + (r*SPH + ct)*2, vg + (size_t)r*HD + ct);
        }
        CP_COMMIT;
    }

    float o[2][4][4];
    #pragma unroll
    for (int i = 0; i < 2; ++i)
        #pragma unroll
        for (int j = 0; j < 4; ++j)
            #pragma unroll
            for (int k = 0; k < 4; ++k) o[i][j][k] = 0.f;
    float dacc[2][4] = {};

    for (int kt = 0; kt < SS/64; ++kt) {
        __syncthreads();   // prev compute done -> safe to fill next buffer / write P
        if (kt + 1 < SS/64) {
            const int nb = (kt + 1) & 1;
            const __half* kg = g_Kh + base + (size_t)(kt + 1)*64*HD;
            const __half* vg = g_Vh + base + (size_t)(kt + 1)*64*HD;
            #pragma unroll
            for (int i = 0; i < 2; ++i) {
                int r = rt + i*32;
                CP_ASYNC16(kbase + ((nb*64 + r)*SPH + ct)*2, kg + (size_t)r*HD + ct);
                CP_ASYNC16(vbase + ((nb*64 + r)*SPH + ct)*2, vg + (size_t)r*HD + ct);
            }
        }
        CP_COMMIT;
        CP_WAIT1;          // tile kt resident
        __syncthreads();

        const unsigned kb = kbase + (kt & 1)*64*SPH*2;
        const unsigned vb = vbase + (kt & 1)*64*SPH*2;

        // S = Q @ K^T (log2-domain scores; Q pre-scaled by log2e/8)
        float s[2][4][4];
        #pragma unroll
        for (int i = 0; i < 2; ++i)
            #pragma unroll
            for (int j = 0; j < 4; ++j)
                #pragma unroll
                for (int k = 0; k < 4; ++k) s[i][j][k] = 0.f;

        #pragma unroll
        for (int ks = 0; ks < 4; ++ks) {
            const int dk = ks * 16;
            #pragma unroll
            for (int fnp = 0; fnp < 2; ++fnp) {
                int row = wn*32 + fnp*16 + (lane & 7) + ((lane >> 4) << 3);
                int col = dk + (((lane >> 3) & 1) << 3);
                unsigned b0, b1, b2, b3;
                ldsm4(b0, b1, b2, b3, kb + (row*SPH + col)*2);
                #pragma unroll
                for (int fm = 0; fm < 2; ++fm) {
                    mma_f16(s[fm][2*fnp    ], qf[fm][ks][0], qf[fm][ks][1], qf[fm][ks][2], qf[fm][ks][3], b0, b1);
                    mma_f16(s[fm][2*fnp + 1], qf[fm][ks][0], qf[fm][ks][1], qf[fm][ks][2], qf[fm][ks][3], b2, b3);
                }
            }
        }

        // P = 2^S via ex2.approx.f16x2, stage to smem (fp16)
        #pragma unroll
        for (int fm = 0; fm < 2; ++fm)
            #pragma unroll
            for (int fn = 0; fn < 4; ++fn) {
                unsigned p01 = ex2h2(packh2(s[fm][fn][0], s[fm][fn][1]));
                unsigned p23 = ex2h2(packh2(s[fm][fn][2], s[fm][fn][3]));
                int row = wm*32 + fm*16 + lr;
                int col = wn*32 + fn*8 + 2*lc;
                *(unsigned*)(Ps + (row    )*SPH + col) = p01;
                *(unsigned*)(Ps + (row + 8)*SPH + col) = p23;
            }
        __syncthreads();   // P complete before cross-warp PV

        // O += P @ V ; denom via ones-column mma (fp32-exact sum of fp16 P).
        // NOTE: the A fragment here spans ALL 64 keys, so dacc is the FULL row
        // sum in each warp — only wn==0 warps may contribute it (see below).
        #pragma unroll
        for (int ks = 0; ks < 4; ++ks) {
            const int kk = ks * 16;
            unsigned a[2][4];
            #pragma unroll
            for (int fm = 0; fm < 2; ++fm) {
                int row = wm*32 + fm*16 + (lane & 15);
                int col = kk + ((lane >> 4) << 3);
                ldsm4(a[fm][0], a[fm][1], a[fm][2], a[fm][3],
                      pbase + (row*SPH + col)*2);
                mma_f16(dacc[fm], a[fm][0], a[fm][1], a[fm][2], a[fm][3], ONESH2, ONESH2);
            }
            #pragma unroll
            for (int fnp = 0; fnp < 2; ++fnp) {
                int row = kk + (lane & 7) + (((lane >> 3) & 1) << 3);
                int col = wn*32 + fnp*16 + ((lane >> 4) << 3);
                unsigned b0, b1, b2, b3;
                ldsm4t(b0, b1, b2, b3, vb + (row*SPH + col)*2);
                #pragma unroll
                for (int fm = 0; fm < 2; ++fm) {
                    mma_f16(o[fm][2*fnp    ], a[fm][0], a[fm][1], a[fm][2], a[fm][3], b0, b1);
                    mma_f16(o[fm][2*fnp + 1], a[fm][0], a[fm][1], a[fm][2], a[fm][3], b2, b3);
                }
            }
        }
    }

    // publish row sums: dacc already holds the FULL row sum (all keys) in every
    // warp; exactly one warp per row-group (wn==0) writes it. Plain store.
    __syncthreads();
    if (wn == 0 && lc == 0) {
        #pragma unroll
        for (int fm = 0; fm < 2; ++fm) {
            dss[wm*32 + fm*16 + lr    ] = dacc[fm][0];
            dss[wm*32 + fm*16 + lr + 8] = dacc[fm][2];
        }
    }
    __syncthreads();

    #pragma unroll
    for (int fm = 0; fm < 2; ++fm)
        #pragma unroll
        for (int fn = 0; fn < 4; ++fn) {
            int row0 = wm*32 + fm*16 + lr;
            int col  = wn*32 + fn*8 + 2*lc;
            float inv0 = 1.0f / dss[row0];
            float inv1 = 1.0f / dss[row0 + 8];
            float2 v0 = make_float2(o[fm][fn][0]*inv0, o[fm][fn][1]*inv0);
            float2 v1 = make_float2(o[fm][fn][2]*inv1, o[fm][fn][3]*inv1);
            *(float2*)(out + (size_t)(b*SS + q0 + row0    )*DD + h*HD + col) = v0;
            *(float2*)(out + (size_t)(b*SS + q0 + row0 + 8)*DD + h*HD + col) = v1;
        }
}

// ---------------------------------------------------------------------------
extern "C" void kernel_launch(void* const* d_in, const int* in_sizes, int n_in,
                              void* d_out, int out_size)
{
    const float* X  = (const float*)d_in[0];
    const float* Wq = (const float*)d_in[1];
    const float* bq = (const float*)d_in[2];
    const float* Wk = (const float*)d_in[3];
    const float* bk = (const float*)d_in[4];
    const float* Wv = (const float*)d_in[5];
    const float* bv = (const float*)d_in[6];
    float* out = (float*)d_out;

    cvt_all_kernel<<<1024, 256>>>((const float4*)X, (const float4*)Wq,
                                  (const float4*)Wk, (const float4*)Wv);
    rope_kernel<<<SS*32/256, 256>>>();

    dim3 g1(HH, NTOK/128);         // (20, 32)
    proj_kernel<<<g1, 256>>>(bq, bk, bv);

    const int attn_smem = (128*SPH + 4*64*SPH)*2 + 128*4;   // 55808 B
    cudaFuncSetAttribute(attn_kernel, cudaFuncAttributeMaxDynamicSharedMemorySize, attn_smem);
    dim3 g2(SS/128, BB*HH);        // (16, 40)
    attn_kernel<<<g2, 256, attn_smem>>>(out);
}

// round 9
// speedup vs baseline: 8.4329x; 1.1896x over previous
#include <cuda_runtime.h>
#include <cuda_fp16.h>
#include <math.h>

#define BB 2
#define SS 2048
#define DD 1280
#define HH 20
#define HD 64
#define NTOK (BB*SS)   // 4096

// fp16 scratch
__device__ __half g_Xh[NTOK*DD];          // hidden states, fp16
__device__ __half g_Wh[3*DD*DD];          // Wq|Wk|Wv, fp16
__device__ __half g_Qh[BB*HH*SS*HD];      // [b][h][s][hd]  (Q pre-scaled by log2e/8)
__device__ __half g_Kh[BB*HH*SS*HD];
__device__ __half g_Vh[BB*HH*SS*HD];
__device__ float2 g_rope[SS*32];          // (cos, sin) per (s, jj)

// ---------------------------------------------------------------------------
// helpers
// ---------------------------------------------------------------------------
__device__ __forceinline__ unsigned s2u(const void* p) {
    return (unsigned)__cvta_generic_to_shared(p);
}
__device__ __forceinline__ unsigned packh2(float x, float y) {
    __half2 h = __floats2half2_rn(x, y);
    return *(unsigned*)&h;
}
__device__ __forceinline__ unsigned ex2h2(unsigned a) {
    unsigned d;
    asm volatile("ex2.approx.f16x2 %0, %1;" : "=r"(d) : "r"(a));
    return d;
}
__device__ __forceinline__ void mma_f16(float c[4],
                                        unsigned a0, unsigned a1, unsigned a2, unsigned a3,
                                        unsigned b0, unsigned b1) {
    asm volatile(
        "mma.sync.aligned.m16n8k16.row.col.f32.f16.f16.f32 "
        "{%0,%1,%2,%3},{%4,%5,%6,%7},{%8,%9},{%0,%1,%2,%3};\n"
        : "+f"(c[0]), "+f"(c[1]), "+f"(c[2]), "+f"(c[3])
        : "r"(a0), "r"(a1), "r"(a2), "r"(a3), "r"(b0), "r"(b1));
}
__device__ __forceinline__ void ldsm4(unsigned& r0, unsigned& r1, unsigned& r2, unsigned& r3,
                                      unsigned addr) {
    asm volatile("ldmatrix.sync.aligned.m8n8.x4.shared.b16 {%0,%1,%2,%3},[%4];"
                 : "=r"(r0), "=r"(r1), "=r"(r2), "=r"(r3) : "r"(addr));
}
__device__ __forceinline__ void ldsm4t(unsigned& r0, unsigned& r1, unsigned& r2, unsigned& r3,
                                       unsigned addr) {
    asm volatile("ldmatrix.sync.aligned.m8n8.x4.trans.shared.b16 {%0,%1,%2,%3},[%4];"
                 : "=r"(r0), "=r"(r1), "=r"(r2), "=r"(r3) : "r"(addr));
}
#define CP_ASYNC16(sm, gp) \
    asm volatile("cp.async.cg.shared.global [%0],[%1],16;\n" :: "r"(sm), "l"(gp))
#define CP_COMMIT  asm volatile("cp.async.commit_group;\n" ::: "memory")
#define CP_WAIT1   asm volatile("cp.async.wait_group 1;\n" ::: "memory")

// ---------------------------------------------------------------------------
// Kernel 0a: fp32 -> fp16 conversion of X, Wq, Wk, Wv (single launch)
// ---------------------------------------------------------------------------
#define N4X (NTOK*DD/4)
#define N4W (DD*DD/4)
__global__ void cvt_all_kernel(const float4* __restrict__ X,
                               const float4* __restrict__ Wq,
                               const float4* __restrict__ Wk,
                               const float4* __restrict__ Wv)
{
    int i = blockIdx.x*blockDim.x + threadIdx.x;
    int stride = gridDim.x*blockDim.x;
    const int tot = N4X + 3*N4W;
    for (; i < tot; i += stride) {
        const float4* src;
        uint2* dst;
        int j;
        if (i < N4X)            { src = X;  dst = (uint2*)g_Xh; j = i; }
        else if (i < N4X+N4W)   { src = Wq; dst = (uint2*)g_Wh; j = i - N4X; }
        else if (i < N4X+2*N4W) { src = Wk; dst = (uint2*)(g_Wh + (size_t)DD*DD);   j = i - N4X - N4W; }
        else                    { src = Wv; dst = (uint2*)(g_Wh + (size_t)2*DD*DD); j = i - N4X - 2*N4W; }
        float4 v = src[j];
        uint2 r;
        r.x = packh2(v.x, v.y);
        r.y = packh2(v.z, v.w);
        dst[j] = r;
    }
}

// Kernel 0b: RoPE table
__global__ void rope_kernel()
{
    int idx = blockIdx.x*blockDim.x + threadIdx.x;
    if (idx >= SS*32) return;
    int s = idx >> 5, jj = idx & 31;
    const float L2C = 0.41524101186092029f;  // log2(10000)/32
    float invf = exp2f(-(float)jj * L2C);
    float sn, cs;
    sincosf((float)s * invf, &sn, &cs);
    g_rope[idx] = make_float2(cs, sn);
}

// ---------------------------------------------------------------------------
// Kernel 1: fused QKV projection (Q,K,V per block, shared X stage).
//   grid (20 heads, 32 mtiles). Block tile 128x64 per z, warp tile 32x32.
//   cp.async double-buffered X/W staging; 2 CTAs/SM.
//   Q output pre-scaled by (1/8)*log2(e) so attention scores are log2-domain.
// ---------------------------------------------------------------------------
#define APADH 40   // halves per As row (80B stride)
#define WPADH 72   // halves per Ws row (144B stride)
#define ASZ (128*APADH*2)       // 10240 B per As buffer
#define WSZ (3*32*WPADH*2)      // 13824 B per Ws buffer

__global__ __launch_bounds__(256, 2) void proj_kernel(
    const float* __restrict__ bq, const float* __restrict__ bk,
    const float* __restrict__ bv)
{
    __shared__ __align__(16) char smbuf[2*ASZ + 2*WSZ];   // 48128 B (union w/ stage)
    float* stage = (float*)smbuf;                          // [128][65] (33280 B)

    const int t    = threadIdx.x;
    const int lane = t & 31;
    const int wid  = t >> 5;
    const int wm   = wid >> 1;     // 0..3
    const int wn   = wid & 1;      // 0..1
    const int m0   = blockIdx.y * 128;
    const int h    = blockIdx.x;
    const int n0   = h * 64;
    const int lr = lane >> 2, lc = lane & 3;

    const unsigned abase = s2u(smbuf);             // As[2]
    const unsigned wbase = abase + 2*ASZ;          // Ws[2]

    // cp.async chunk mappings
    const int xr = t >> 2, xc = (t & 3) * 8;       // X: 512 chunks, 2/thread (r=idx>>2)
    const int widx_z = (256 + t) >> 8;             // helper below instead

    float acc[3][2][4][4];
    #pragma unroll
    for (int z = 0; z < 3; ++z)
        #pragma unroll
        for (int i = 0; i < 2; ++i)
            #pragma unroll
            for (int j = 0; j < 4; ++j)
                #pragma unroll
                for (int k = 0; k < 4; ++k) acc[z][i][j][k] = 0.f;

    // preload tile 0 into buffer 0
    {
        #pragma unroll
        for (int i = 0; i < 2; ++i) {
            int idx = t + i*256;
            int r = idx >> 2, c8 = (idx & 3) * 8;
            CP_ASYNC16(abase + (r*APADH + c8)*2,
                       g_Xh + (size_t)(m0 + r)*DD + c8);
        }
        #pragma unroll
        for (int i = 0; i < 3; ++i) {
            int idx = t + i*256;
            int z = idx >> 8, rem = idx & 255;
            int r = rem >> 3, c8 = (rem & 7) * 8;
            CP_ASYNC16(wbase + (z*32*WPADH + r*WPADH + c8)*2,
                       g_Wh + (size_t)z*DD*DD + (size_t)r*DD + n0 + c8);
        }
        CP_COMMIT;
    }

    for (int kt = 0; kt < 40; ++kt) {
        __syncthreads();   // prev compute done -> safe to overwrite other buffer
        if (kt < 39) {
            const int nb = (kt + 1) & 1;
            const int k0 = (kt + 1) * 32;
            #pragma unroll
            for (int i = 0; i < 2; ++i) {
                int idx = t + i*256;
                int r = idx >> 2, c8 = (idx & 3) * 8;
                CP_ASYNC16(abase + nb*ASZ + (r*APADH + c8)*2,
                           g_Xh + (size_t)(m0 + r)*DD + k0 + c8);
            }
            #pragma unroll
            for (int i = 0; i < 3; ++i) {
                int idx = t + i*256;
                int z = idx >> 8, rem = idx & 255;
                int r = rem >> 3, c8 = (rem & 7) * 8;
                CP_ASYNC16(wbase + nb*WSZ + (z*32*WPADH + r*WPADH + c8)*2,
                           g_Wh + (size_t)z*DD*DD + (size_t)(k0 + r)*DD + n0 + c8);
            }
        }
        CP_COMMIT;
        CP_WAIT1;          // tile kt resident
        __syncthreads();

        const unsigned ab = abase + (kt & 1)*ASZ;
        const unsigned wb = wbase + (kt & 1)*WSZ;

        #pragma unroll
        for (int ks = 0; ks < 2; ++ks) {
            const int kk = ks * 16;
            unsigned a[2][4];
            #pragma unroll
            for (int fm = 0; fm < 2; ++fm) {
                int row = wm*32 + fm*16 + (lane & 15);
                int col = kk + ((lane >> 4) << 3);
                ldsm4(a[fm][0], a[fm][1], a[fm][2], a[fm][3],
                      ab + (row*APADH + col)*2);
            }
            #pragma unroll
            for (int z = 0; z < 3; ++z) {
                #pragma unroll
                for (int fnp = 0; fnp < 2; ++fnp) {
                    int row = kk + (lane & 7) + (((lane >> 3) & 1) << 3);
                    int col = wn*32 + fnp*16 + ((lane >> 4) << 3);
                    unsigned b0, b1, b2, b3;
                    ldsm4t(b0, b1, b2, b3,
                           wb + (z*32*WPADH + row*WPADH + col)*2);
                    #pragma unroll
                    for (int fm = 0; fm < 2; ++fm) {
                        mma_f16(acc[z][fm][2*fnp    ], a[fm][0], a[fm][1], a[fm][2], a[fm][3], b0, b1);
                        mma_f16(acc[z][fm][2*fnp + 1], a[fm][0], a[fm][1], a[fm][2], a[fm][3], b2, b3);
                    }
                }
            }
        }
    }

    // --- epilogues ---
    // Q then K: stage fp32, RoPE via table, store fp16.
    // Q scale folds in log2(e) so downstream softmax can use ex2.
    #pragma unroll
    for (int z = 0; z < 2; ++z) {
        const float* bias = z ? bk : bq;
        __half* dst       = z ? g_Kh : g_Qh;
        const float scale = z ? 1.0f : 0.125f * 1.4426950408889634f;
        __syncthreads();
        #pragma unroll
        for (int fm = 0; fm < 2; ++fm)
            #pragma unroll
            for (int fn = 0; fn < 4; ++fn)
                #pragma unroll
                for (int k = 0; k < 4; ++k) {
                    int row = wm*32 + fm*16 + lr + ((k >= 2) ? 8 : 0);
                    int col = wn*32 + fn*8 + 2*lc + (k & 1);
                    stage[row*65 + col] = (acc[z][fm][fn][k] + bias[n0 + col]) * scale;
                }
        __syncthreads();
        #pragma unroll
        for (int i = 0; i < 16; ++i) {
            int idx = t + i*256;          // 128 x 32 col-pairs
            int r = idx >> 5, c = (idx & 31) * 2;
            float v0 = stage[r*65 + c];
            float v1 = stage[r*65 + c + 1];
            float p0 = stage[r*65 + ((c + 32) & 63)];
            float p1 = stage[r*65 + ((c + 33) & 63)];
            if (c < 32) { p0 = -p0; p1 = -p1; }
            int m = m0 + r, b = m >> 11, s = m & (SS - 1);
            float2 cs0 = g_rope[s*32 + (c & 31)];
            float2 cs1 = g_rope[s*32 + ((c + 1) & 31)];
            float r0 = v0*cs0.x + p0*cs0.y;
            float r1 = v1*cs1.x + p1*cs1.y;
            *(unsigned*)(dst + ((size_t)(b*HH + h)*SS + s)*HD + c) = packh2(r0, r1);
        }
    }
    // V: direct fp16 store
    #pragma unroll
    for (int fm = 0; fm < 2; ++fm)
        #pragma unroll
        for (int fn = 0; fn < 4; ++fn) {
            int row0 = wm*32 + fm*16 + lr;
            int col  = wn*32 + fn*8 + 2*lc;
            float b0 = bv[n0 + col], b1 = bv[n0 + col + 1];
            int m = m0 + row0;
            int b = m >> 11, s = m & (SS - 1);
            *(unsigned*)(g_Vh + ((size_t)(b*HH + h)*SS + s)*HD + col) =
                packh2(acc[2][fm][fn][0] + b0, acc[2][fm][fn][1] + b1);
            m = m0 + row0 + 8;
            b = m >> 11; s = m & (SS - 1);
            *(unsigned*)(g_Vh + ((size_t)(b*HH + h)*SS + s)*HD + col) =
                packh2(acc[2][fm][fn][2] + b0, acc[2][fm][fn][3] + b1);
        }
}

// ---------------------------------------------------------------------------
// Kernel 2: attention. 128 q-rows/block, key chunks of 64, warp tile 32x32.
//   cp.async double-buffered K/V; ex2.f16x2 softmax; denom via ones-column mma.
//   (unchanged from round 8 — known good, 141us)
// ---------------------------------------------------------------------------
#define SPH 72
#define ONESH2 0x3C003C00u
extern __shared__ __half smh[];

__global__ __launch_bounds__(256, 2) void attn_kernel(float* __restrict__ out)
{
    __half* Qs   = smh;                       // [128][SPH]; reused as Ps
    __half* Ps   = smh;
    __half* Kbuf = smh + 128*SPH;             // [2][64][SPH]
    __half* Vbuf = smh + 128*SPH + 2*64*SPH;  // [2][64][SPH]
    float*  dss  = (float*)(smh + 128*SPH + 4*64*SPH);   // [128]

    const int t    = threadIdx.x;
    const int lane = t & 31;
    const int wid  = t >> 5;
    const int wm   = wid >> 1;     // q-row offset 32*wm
    const int wn   = wid & 1;      // key/d offset 32*wn
    const int lr = lane >> 2, lc = lane & 3;

    const int q0 = blockIdx.x * 128;
    const int bh = blockIdx.y;
    const int b  = bh / HH, h = bh % HH;
    const size_t base = (size_t)bh * SS * HD;

    const unsigned pbase = s2u(Ps);
    const unsigned kbase = s2u(Kbuf);
    const unsigned vbase = s2u(Vbuf);

    const int rt = t >> 3, ct = (t & 7) * 8;   // cp.async tile mapping (64 rows x 8 chunks)

    // stage Q (fp16 direct copy)
    #pragma unroll
    for (int i = 0; i < 4; ++i) {
        int idx = t + i*256;
        int r = idx >> 3, c8 = idx & 7;
        *(uint4*)(Qs + r*SPH + c8*8) =
            *(const uint4*)(g_Qh + base + (size_t)(q0 + r)*HD + c8*8);
    }
    __syncthreads();

    unsigned qf[2][4][4];
    #pragma unroll
    for (int fm = 0; fm < 2; ++fm)
        #pragma unroll
        for (int ks = 0; ks < 4; ++ks) {
            int row = wm*32 + fm*16 + (lane & 15);
            int col = ks*16 + ((lane >> 4) << 3);
            ldsm4(qf[fm][ks][0], qf[fm][ks][1], qf[fm][ks][2], qf[fm][ks][3],
                  pbase + (row*SPH + col)*2);
        }
    __syncthreads();   // frag reads done before Ps overwrites Qs

    // preload tile 0 into buffer 0
    {
        const __half* kg = g_Kh + base;
        const __half* vg = g_Vh + base;
        #pragma unroll
        for (int i = 0; i < 2; ++i) {
            int r = rt + i*32;
            CP_ASYNC16(kbase + (r*SPH + ct)*2, kg + (size_t)r*HD + ct);
            CP_ASYNC16(vbase + (r*SPH + ct)*2, vg + (size_t)r*HD + ct);
        }
        CP_COMMIT;
    }

    float o[2][4][4];
    #pragma unroll
    for (int i = 0; i < 2; ++i)
        #pragma unroll
        for (int j = 0; j < 4; ++j)
            #pragma unroll
            for (int k = 0; k < 4; ++k) o[i][j][k] = 0.f;
    float dacc[2][4] = {};

    for (int kt = 0; kt < SS/64; ++kt) {
        __syncthreads();   // prev compute done -> safe to fill next buffer / write P
        if (kt + 1 < SS/64) {
            const int nb = (kt + 1) & 1;
            const __half* kg = g_Kh + base + (size_t)(kt + 1)*64*HD;
            const __half* vg = g_Vh + base + (size_t)(kt + 1)*64*HD;
            #pragma unroll
            for (int i = 0; i < 2; ++i) {
                int r = rt + i*32;
                CP_ASYNC16(kbase + ((nb*64 + r)*SPH + ct)*2, kg + (size_t)r*HD + ct);
                CP_ASYNC16(vbase + ((nb*64 + r)*SPH + ct)*2, vg + (size_t)r*HD + ct);
            }
        }
        CP_COMMIT;
        CP_WAIT1;          // tile kt resident
        __syncthreads();

        const unsigned kb = kbase + (kt & 1)*64*SPH*2;
        const unsigned vb = vbase + (kt & 1)*64*SPH*2;

        // S = Q @ K^T (log2-domain scores; Q pre-scaled by log2e/8)
        float s[2][4][4];
        #pragma unroll
        for (int i = 0; i < 2; ++i)
            #pragma unroll
            for (int j = 0; j < 4; ++j)
                #pragma unroll
                for (int k = 0; k < 4; ++k) s[i][j][k] = 0.f;

        #pragma unroll
        for (int ks = 0; ks < 4; ++ks) {
            const int dk = ks * 16;
            #pragma unroll
            for (int fnp = 0; fnp < 2; ++fnp) {
                int row = wn*32 + fnp*16 + (lane & 7) + ((lane >> 4) << 3);
                int col = dk + (((lane >> 3) & 1) << 3);
                unsigned b0, b1, b2, b3;
                ldsm4(b0, b1, b2, b3, kb + (row*SPH + col)*2);
                #pragma unroll
                for (int fm = 0; fm < 2; ++fm) {
                    mma_f16(s[fm][2*fnp    ], qf[fm][ks][0], qf[fm][ks][1], qf[fm][ks][2], qf[fm][ks][3], b0, b1);
                    mma_f16(s[fm][2*fnp + 1], qf[fm][ks][0], qf[fm][ks][1], qf[fm][ks][2], qf[fm][ks][3], b2, b3);
                }
            }
        }

        // P = 2^S via ex2.approx.f16x2, stage to smem (fp16)
        #pragma unroll
        for (int fm = 0; fm < 2; ++fm)
            #pragma unroll
            for (int fn = 0; fn < 4; ++fn) {
                unsigned p01 = ex2h2(packh2(s[fm][fn][0], s[fm][fn][1]));
                unsigned p23 = ex2h2(packh2(s[fm][fn][2], s[fm][fn][3]));
                int row = wm*32 + fm*16 + lr;
                int col = wn*32 + fn*8 + 2*lc;
                *(unsigned*)(Ps + (row    )*SPH + col) = p01;
                *(unsigned*)(Ps + (row + 8)*SPH + col) = p23;
            }
        __syncthreads();   // P complete before cross-warp PV

        // O += P @ V ; denom via ones-column mma (fp32-exact sum of fp16 P).
        // A fragment spans ALL 64 keys -> dacc is the FULL row sum in each warp.
        #pragma unroll
        for (int ks = 0; ks < 4; ++ks) {
            const int kk = ks * 16;
            unsigned a[2][4];
            #pragma unroll
            for (int fm = 0; fm < 2; ++fm) {
                int row = wm*32 + fm*16 + (lane & 15);
                int col = kk + ((lane >> 4) << 3);
                ldsm4(a[fm][0], a[fm][1], a[fm][2], a[fm][3],
                      pbase + (row*SPH + col)*2);
                mma_f16(dacc[fm], a[fm][0], a[fm][1], a[fm][2], a[fm][3], ONESH2, ONESH2);
            }
            #pragma unroll
            for (int fnp = 0; fnp < 2; ++fnp) {
                int row = kk + (lane & 7) + (((lane >> 3) & 1) << 3);
                int col = wn*32 + fnp*16 + ((lane >> 4) << 3);
                unsigned b0, b1, b2, b3;
                ldsm4t(b0, b1, b2, b3, vb + (row*SPH + col)*2);
                #pragma unroll
                for (int fm = 0; fm < 2; ++fm) {
                    mma_f16(o[fm][2*fnp    ], a[fm][0], a[fm][1], a[fm][2], a[fm][3], b0, b1);
                    mma_f16(o[fm][2*fnp + 1], a[fm][0], a[fm][1], a[fm][2], a[fm][3], b2, b3);
                }
            }
        }
    }

    // publish row sums: only wn==0 writes (dacc is already the full row sum).
    __syncthreads();
    if (wn == 0 && lc == 0) {
        #pragma unroll
        for (int fm = 0; fm < 2; ++fm) {
            dss[wm*32 + fm*16 + lr    ] = dacc[fm][0];
            dss[wm*32 + fm*16 + lr + 8] = dacc[fm][2];
        }
    }
    __syncthreads();

    #pragma unroll
    for (int fm = 0; fm < 2; ++fm)
        #pragma unroll
        for (int fn = 0; fn < 4; ++fn) {
            int row0 = wm*32 + fm*16 + lr;
            int col  = wn*32 + fn*8 + 2*lc;
            float inv0 = 1.0f / dss[row0];
            float inv1 = 1.0f / dss[row0 + 8];
            float2 v0 = make_float2(o[fm][fn][0]*inv0, o[fm][fn][1]*inv0);
            float2 v1 = make_float2(o[fm][fn][2]*inv1, o[fm][fn][3]*inv1);
            *(float2*)(out + (size_t)(b*SS + q0 + row0    )*DD + h*HD + col) = v0;
            *(float2*)(out + (size_t)(b*SS + q0 + row0 + 8)*DD + h*HD + col) = v1;
        }
}

// ---------------------------------------------------------------------------
extern "C" void kernel_launch(void* const* d_in, const int* in_sizes, int n_in,
                              void* d_out, int out_size)
{
    const float* X  = (const float*)d_in[0];
    const float* Wq = (const float*)d_in[1];
    const float* bq = (const float*)d_in[2];
    const float* Wk = (const float*)d_in[3];
    const float* bk = (const float*)d_in[4];
    const float* Wv = (const float*)d_in[5];
    const float* bv = (const float*)d_in[6];
    float* out = (float*)d_out;

    cvt_all_kernel<<<1024, 256>>>((const float4*)X, (const float4*)Wq,
                                  (const float4*)Wk, (const float4*)Wv);
    rope_kernel<<<SS*32/256, 256>>>();

    dim3 g1(HH, NTOK/128);         // (20, 32)
    proj_kernel<<<g1, 256>>>(bq, bk, bv);

    const int attn_smem = (128*SPH + 4*64*SPH)*2 + 128*4;   // 55808 B
    cudaFuncSetAttribute(attn_kernel, cudaFuncAttributeMaxDynamicSharedMemorySize, attn_smem);
    dim3 g2(SS/128, BB*HH);        // (16, 40)
    attn_kernel<<<g2, 256, attn_smem>>>(out);
}